// round 2
// baseline (speedup 1.0000x reference)
#include <cuda_runtime.h>
#include <cuda_bf16.h>

#define B 2
#define S 2048
#define E 1024
#define H 16
#define D 64
#define BH (B*H)            // 32
#define NROW (B*S*H)        // 65536

// Scratch (allocation-free rule: __device__ globals)
__device__ float g_q[B*H*S*D];
__device__ float g_k[B*H*S*D];
__device__ float g_v[B*H*S*D];
__device__ float g_att[B*S*E];

#define PAD 68  // floats per shared row (16B aligned, phase-optimal for tx+16j row access)

// =====================================================================
// Kernel 1: QKV projection.  x viewed as 65536 rows of 64 (b,s,h order).
// q[b,h,s,e] = sum_d x[b,s,h*64+d] * Wq[e][d]   (torch Linear: x @ W^T)
// =====================================================================
#define K1_ROWS 16
#define QKV_SMEM ((3*64*PAD + K1_ROWS*64) * 4)

__global__ void __launch_bounds__(256) qkv_kernel(const float* __restrict__ x,
                                                  const float* __restrict__ Wq,
                                                  const float* __restrict__ Wk,
                                                  const float* __restrict__ Wv) {
    extern __shared__ float sm[];
    float* sWq = sm;
    float* sWk = sWq + 64*PAD;
    float* sWv = sWk + 64*PAD;
    float* sX  = sWv + 64*PAD;       // [16][64]

    const int tid = threadIdx.x;
    const int r   = tid >> 4;        // row within block (0..15)
    const int c   = tid & 15;        // output-lane (0..15)

    // Load weights into padded shared (rows = e, cols = k)
    for (int i = tid; i < 1024; i += 256) {
        int e = i >> 4, k4 = (i & 15) << 2;
        *(float4*)(sWq + e*PAD + k4) = *(const float4*)(Wq + e*64 + k4);
        *(float4*)(sWk + e*PAD + k4) = *(const float4*)(Wk + e*64 + k4);
        *(float4*)(sWv + e*PAD + k4) = *(const float4*)(Wv + e*64 + k4);
    }
    const int g0 = blockIdx.x * K1_ROWS;
    {
        int rr = tid >> 4, k4 = (tid & 15) << 2;
        *(float4*)(sX + rr*64 + k4) = *(const float4*)(x + (size_t)(g0 + rr)*64 + k4);
    }
    __syncthreads();

    float aq[4] = {0,0,0,0}, ak[4] = {0,0,0,0}, av[4] = {0,0,0,0};
    #pragma unroll 4
    for (int kk = 0; kk < 64; kk += 4) {
        float4 xv = *(const float4*)(sX + r*64 + kk);
        #pragma unroll
        for (int j = 0; j < 4; j++) {
            int e = c + 16*j;
            float4 wq = *(const float4*)(sWq + e*PAD + kk);
            float4 wk = *(const float4*)(sWk + e*PAD + kk);
            float4 wv = *(const float4*)(sWv + e*PAD + kk);
            aq[j] += xv.x*wq.x + xv.y*wq.y + xv.z*wq.z + xv.w*wq.w;
            ak[j] += xv.x*wk.x + xv.y*wk.y + xv.z*wk.z + xv.w*wk.w;
            av[j] += xv.x*wv.x + xv.y*wv.y + xv.z*wv.z + xv.w*wv.w;
        }
    }

    // Map row g -> (b,s,h); output layout (b,h,s,d)
    int g   = g0 + r;
    int b   = g >> 15;        // / (S*H) = 32768
    int rem = g & 32767;
    int s   = rem >> 4;       // / H
    int h   = rem & 15;
    size_t orow = ((size_t)(b*H + h)*S + s) * 64;
    #pragma unroll
    for (int j = 0; j < 4; j++) {
        int e = c + 16*j;
        g_q[orow + e] = aq[j];
        g_k[orow + e] = ak[j];
        g_v[orow + e] = av[j];
    }
}

// =====================================================================
// Kernel 2: flash attention, fp32.  Br = Bc = 64, D = 64.
// grid (S/64, B*H), block 256 (logical 16x16, 4x4 register micro-tile)
// =====================================================================
#define ATTN_SMEM (4*64*PAD*4)

__global__ void __launch_bounds__(256) attn_kernel() {
    extern __shared__ float sm[];
    float* sQ = sm;
    float* sK = sQ + 64*PAD;
    float* sV = sK + 64*PAD;
    float* sP = sV + 64*PAD;

    const int tid = threadIdx.x;
    const int tx  = tid & 15;
    const int ty  = tid >> 4;
    const int qt  = blockIdx.x;
    const int bh  = blockIdx.y;

    const float* Qg = g_q + (size_t)bh*S*D + (size_t)qt*64*D;
    const float* Kg = g_k + (size_t)bh*S*D;
    const float* Vg = g_v + (size_t)bh*S*D;

    // Load Q tile (64x64) once
    for (int i = tid; i < 1024; i += 256) {
        int r = i >> 4, c4 = (i & 15) << 2;
        *(float4*)(sQ + r*PAD + c4) = *(const float4*)(Qg + r*64 + c4);
    }

    float m[4], l[4], o[4][4];
    #pragma unroll
    for (int i = 0; i < 4; i++) {
        m[i] = -1e30f; l[i] = 0.f;
        #pragma unroll
        for (int j = 0; j < 4; j++) o[i][j] = 0.f;
    }

    const float scale = 0.125f;  // 1/sqrt(64)

    for (int kt = 0; kt < S/64; kt++) {
        __syncthreads();  // previous PV done (and first-iter Q load ordering w/ 2nd sync)
        const float* Kt = Kg + (size_t)kt*64*64;
        const float* Vt = Vg + (size_t)kt*64*64;
        for (int i = tid; i < 1024; i += 256) {
            int r = i >> 4, c4 = (i & 15) << 2;
            *(float4*)(sK + r*PAD + c4) = *(const float4*)(Kt + r*64 + c4);
            *(float4*)(sV + r*PAD + c4) = *(const float4*)(Vt + r*64 + c4);
        }
        __syncthreads();

        // S = Q K^T : thread owns q-rows 4ty+i, k-cols tx+16j
        float sc[4][4];
        #pragma unroll
        for (int i = 0; i < 4; i++)
            #pragma unroll
            for (int j = 0; j < 4; j++) sc[i][j] = 0.f;

        #pragma unroll 2
        for (int kk = 0; kk < 64; kk += 4) {
            float4 qv[4], kv[4];
            #pragma unroll
            for (int i = 0; i < 4; i++) qv[i] = *(const float4*)(sQ + (4*ty+i)*PAD + kk);
            #pragma unroll
            for (int j = 0; j < 4; j++) kv[j] = *(const float4*)(sK + (tx+16*j)*PAD + kk);
            #pragma unroll
            for (int i = 0; i < 4; i++)
                #pragma unroll
                for (int j = 0; j < 4; j++)
                    sc[i][j] += qv[i].x*kv[j].x + qv[i].y*kv[j].y +
                                qv[i].z*kv[j].z + qv[i].w*kv[j].w;
        }

        // Online softmax update per row (reduce across tx within warp halves)
        #pragma unroll
        for (int i = 0; i < 4; i++) {
            float rmax = fmaxf(fmaxf(sc[i][0], sc[i][1]), fmaxf(sc[i][2], sc[i][3]));
            #pragma unroll
            for (int msk = 8; msk >= 1; msk >>= 1)
                rmax = fmaxf(rmax, __shfl_xor_sync(0xffffffffu, rmax, msk));
            float mn   = fmaxf(m[i], rmax);
            float corr = __expf((m[i] - mn) * scale);
            m[i] = mn;
            float rs = 0.f;
            #pragma unroll
            for (int j = 0; j < 4; j++) {
                float p = __expf((sc[i][j] - mn) * scale);
                sP[(4*ty+i)*PAD + tx + 16*j] = p;
                rs += p;
            }
            #pragma unroll
            for (int msk = 8; msk >= 1; msk >>= 1)
                rs += __shfl_xor_sync(0xffffffffu, rs, msk);
            l[i] = l[i]*corr + rs;
            #pragma unroll
            for (int j = 0; j < 4; j++) o[i][j] *= corr;
        }
        __syncthreads();

        // O += P V : thread owns rows 4ty+i, d-cols 4tx+j
        #pragma unroll 2
        for (int cc = 0; cc < 64; cc += 4) {
            float4 pv[4], vv[4];
            #pragma unroll
            for (int i = 0; i < 4; i++) pv[i] = *(const float4*)(sP + (4*ty+i)*PAD + cc);
            #pragma unroll
            for (int c2 = 0; c2 < 4; c2++) vv[c2] = *(const float4*)(sV + (cc+c2)*PAD + 4*tx);
            #pragma unroll
            for (int i = 0; i < 4; i++) {
                float p0 = pv[i].x, p1 = pv[i].y, p2 = pv[i].z, p3 = pv[i].w;
                o[i][0] += p0*vv[0].x + p1*vv[1].x + p2*vv[2].x + p3*vv[3].x;
                o[i][1] += p0*vv[0].y + p1*vv[1].y + p2*vv[2].y + p3*vv[3].y;
                o[i][2] += p0*vv[0].z + p1*vv[1].z + p2*vv[2].z + p3*vv[3].z;
                o[i][3] += p0*vv[0].w + p1*vv[1].w + p2*vv[2].w + p3*vv[3].w;
            }
        }
    }

    // Epilogue: normalize & write in (b, s, e) layout
    const int b = bh >> 4, h = bh & 15;
    #pragma unroll
    for (int i = 0; i < 4; i++) {
        int srow = qt*64 + 4*ty + i;
        float inv = 1.0f / l[i];
        float4 val = make_float4(o[i][0]*inv, o[i][1]*inv, o[i][2]*inv, o[i][3]*inv);
        *(float4*)(g_att + ((size_t)(b*S + srow))*E + h*64 + 4*tx) = val;
    }
}

// =====================================================================
// Kernel 3: output projection  out = A @ Wo^T + bo  (A = g_att, 4096x1024)
// grid (E/64, (B*S)/64), block 256, 64x64 tiles, K loop over 1024
// =====================================================================
__global__ void __launch_bounds__(256) oproj_kernel(const float* __restrict__ Wo,
                                                    const float* __restrict__ bo,
                                                    float* __restrict__ out) {
    __shared__ float sA[64*PAD];
    __shared__ float sW[64*PAD];
    const int tid = threadIdx.x;
    const int tx  = tid & 15;
    const int ty  = tid >> 4;
    const int e0  = blockIdx.x * 64;
    const int m0  = blockIdx.y * 64;

    float acc[4][4];
    #pragma unroll
    for (int i = 0; i < 4; i++)
        #pragma unroll
        for (int j = 0; j < 4; j++) acc[i][j] = 0.f;

    for (int kc = 0; kc < E; kc += 64) {
        __syncthreads();
        for (int i = tid; i < 1024; i += 256) {
            int r = i >> 4, c4 = (i & 15) << 2;
            *(float4*)(sA + r*PAD + c4) = *(const float4*)(g_att + (size_t)(m0+r)*E + kc + c4);
            *(float4*)(sW + r*PAD + c4) = *(const float4*)(Wo   + (size_t)(e0+r)*E + kc + c4);
        }
        __syncthreads();

        #pragma unroll 2
        for (int kk = 0; kk < 64; kk += 4) {
            float4 av[4], wv[4];
            #pragma unroll
            for (int i = 0; i < 4; i++) av[i] = *(const float4*)(sA + (4*ty+i)*PAD + kk);
            #pragma unroll
            for (int j = 0; j < 4; j++) wv[j] = *(const float4*)(sW + (tx+16*j)*PAD + kk);
            #pragma unroll
            for (int i = 0; i < 4; i++)
                #pragma unroll
                for (int j = 0; j < 4; j++)
                    acc[i][j] += av[i].x*wv[j].x + av[i].y*wv[j].y +
                                 av[i].z*wv[j].z + av[i].w*wv[j].w;
        }
    }

    float bb[4];
    #pragma unroll
    for (int j = 0; j < 4; j++) bb[j] = bo[e0 + tx + 16*j];
    #pragma unroll
    for (int i = 0; i < 4; i++)
        #pragma unroll
        for (int j = 0; j < 4; j++)
            out[(size_t)(m0 + 4*ty + i)*E + e0 + tx + 16*j] = acc[i][j] + bb[j];
}

// =====================================================================
extern "C" void kernel_launch(void* const* d_in, const int* in_sizes, int n_in,
                              void* d_out, int out_size) {
    const float* x  = (const float*)d_in[0];
    const float* Wq = (const float*)d_in[1];
    const float* Wk = (const float*)d_in[2];
    const float* Wv = (const float*)d_in[3];
    const float* Wo = (const float*)d_in[4];
    const float* bo = (const float*)d_in[5];
    float* out = (float*)d_out;

    // Idempotent, deterministic, not stream ops (capture-safe). Called every time.
    cudaFuncSetAttribute(qkv_kernel,  cudaFuncAttributeMaxDynamicSharedMemorySize, QKV_SMEM);
    cudaFuncSetAttribute(attn_kernel, cudaFuncAttributeMaxDynamicSharedMemorySize, ATTN_SMEM);

    qkv_kernel<<<NROW / K1_ROWS, 256, QKV_SMEM>>>(x, Wq, Wk, Wv);
    attn_kernel<<<dim3(S/64, BH), 256, ATTN_SMEM>>>();
    oproj_kernel<<<dim3(E/64, (B*S)/64), 256>>>(Wo, bo, out);
}

// round 3
// speedup vs baseline: 1.9737x; 1.9737x over previous
#include <cuda_runtime.h>
#include <cuda_bf16.h>
#include <cstdint>

#define B 2
#define S 2048
#define E 1024
#define H 16
#define D 64
#define BH (B*H)            // 32
#define NROW (B*S*H)        // 65536

// Scratch (allocation-free rule: __device__ globals)
__device__ float g_q[B*H*S*D];
__device__ float g_k[B*H*S*D];
__device__ float g_v[B*H*S*D];
__device__ float g_att[B*S*E];

#define PAD 68  // fp32 qkv kernel shared stride

// ---------------------------------------------------------------------
// tf32 helpers
// ---------------------------------------------------------------------
__device__ __forceinline__ uint32_t f2t(float f) {
    uint32_t u;
    asm("cvt.rna.tf32.f32 %0, %1;" : "=r"(u) : "f"(f));
    return u;
}

__device__ __forceinline__ void mma8(float* c, uint32_t a0, uint32_t a1,
                                     uint32_t a2, uint32_t a3,
                                     uint32_t b0, uint32_t b1) {
    asm volatile(
        "mma.sync.aligned.m16n8k8.row.col.f32.tf32.tf32.f32 "
        "{%0,%1,%2,%3},{%4,%5,%6,%7},{%8,%9},{%0,%1,%2,%3};"
        : "+f"(c[0]), "+f"(c[1]), "+f"(c[2]), "+f"(c[3])
        : "r"(a0), "r"(a1), "r"(a2), "r"(a3), "r"(b0), "r"(b1));
}

// =====================================================================
// Kernel 1: QKV projection (fp32 FFMA, unchanged from R1 — exact).
// =====================================================================
#define K1_ROWS 16
#define QKV_SMEM ((3*64*PAD + K1_ROWS*64) * 4)

__global__ void __launch_bounds__(256) qkv_kernel(const float* __restrict__ x,
                                                  const float* __restrict__ Wq,
                                                  const float* __restrict__ Wk,
                                                  const float* __restrict__ Wv) {
    extern __shared__ float sm[];
    float* sWq = sm;
    float* sWk = sWq + 64*PAD;
    float* sWv = sWk + 64*PAD;
    float* sX  = sWv + 64*PAD;

    const int tid = threadIdx.x;
    const int r   = tid >> 4;
    const int c   = tid & 15;

    for (int i = tid; i < 1024; i += 256) {
        int e = i >> 4, k4 = (i & 15) << 2;
        *(float4*)(sWq + e*PAD + k4) = *(const float4*)(Wq + e*64 + k4);
        *(float4*)(sWk + e*PAD + k4) = *(const float4*)(Wk + e*64 + k4);
        *(float4*)(sWv + e*PAD + k4) = *(const float4*)(Wv + e*64 + k4);
    }
    const int g0 = blockIdx.x * K1_ROWS;
    {
        int rr = tid >> 4, k4 = (tid & 15) << 2;
        *(float4*)(sX + rr*64 + k4) = *(const float4*)(x + (size_t)(g0 + rr)*64 + k4);
    }
    __syncthreads();

    float aq[4] = {0,0,0,0}, ak[4] = {0,0,0,0}, av[4] = {0,0,0,0};
    #pragma unroll 4
    for (int kk = 0; kk < 64; kk += 4) {
        float4 xv = *(const float4*)(sX + r*64 + kk);
        #pragma unroll
        for (int j = 0; j < 4; j++) {
            int e = c + 16*j;
            float4 wq = *(const float4*)(sWq + e*PAD + kk);
            float4 wk = *(const float4*)(sWk + e*PAD + kk);
            float4 wv = *(const float4*)(sWv + e*PAD + kk);
            aq[j] += xv.x*wq.x + xv.y*wq.y + xv.z*wq.z + xv.w*wq.w;
            ak[j] += xv.x*wk.x + xv.y*wk.y + xv.z*wk.z + xv.w*wk.w;
            av[j] += xv.x*wv.x + xv.y*wv.y + xv.z*wv.z + xv.w*wv.w;
        }
    }

    int g   = g0 + r;
    int b   = g >> 15;
    int rem = g & 32767;
    int s   = rem >> 4;
    int h   = rem & 15;
    size_t orow = ((size_t)(b*H + h)*S + s) * 64;
    #pragma unroll
    for (int j = 0; j < 4; j++) {
        int e = c + 16*j;
        g_q[orow + e] = aq[j];
        g_k[orow + e] = ak[j];
        g_v[orow + e] = av[j];
    }
}

// =====================================================================
// Kernel 2: flash attention on tensor cores (tf32 mma.sync m16n8k8).
// Br = 128 q-rows per block, Bc = 64 kv per tile. 8 warps; warp w owns
// q-rows [16w, 16w+16). grid (S/128, B*H), block 256.
// smem stride 68 -> conflict-free fragment loads (bank = (4g+c)%32).
// =====================================================================
#define AST 68
#define ATTN_SMEM ((128*AST + 64*AST + 64*AST + 128*AST) * 4)

__global__ void __launch_bounds__(256, 2) attn_kernel() {
    extern __shared__ uint32_t smu[];
    uint32_t* sQ = smu;              // [128][68] tf32
    uint32_t* sK = sQ + 128*AST;     // [64][68]  tf32, layout [kv][d]
    uint32_t* sV = sK + 64*AST;      // [64][68]  tf32, layout [kv][d]
    uint32_t* sP = sV + 64*AST;      // [128][68] tf32

    const int tid  = threadIdx.x;
    const int w    = tid >> 5;
    const int lane = tid & 31;
    const int g    = lane >> 2;
    const int tg   = lane & 3;
    const int qt   = blockIdx.x;
    const int bh   = blockIdx.y;

    const float* Qg = g_q + (size_t)bh*S*D + (size_t)qt*128*D;
    const float* Kg = g_k + (size_t)bh*S*D;
    const float* Vg = g_v + (size_t)bh*S*D;

    // Load + convert Q tile (128x64) once
    for (int i = tid; i < 2048; i += 256) {
        int r = i >> 4, c4 = (i & 15) << 2;
        float4 v = *(const float4*)(Qg + r*64 + c4);
        uint32_t* dst = sQ + r*AST + c4;
        dst[0] = f2t(v.x); dst[1] = f2t(v.y); dst[2] = f2t(v.z); dst[3] = f2t(v.w);
    }

    const int r0 = 16*w + g;         // first owned q-row (local)
    float m0 = -1e30f, m1 = -1e30f, l0 = 0.f, l1 = 0.f;
    float o[8][4];
    #pragma unroll
    for (int nt = 0; nt < 8; nt++)
        #pragma unroll
        for (int j = 0; j < 4; j++) o[nt][j] = 0.f;

    const float scale = 0.125f;      // 1/sqrt(64)

    for (int kt = 0; kt < S/64; kt++) {
        __syncthreads();             // prior PV reads of sK/sV complete
        const float* Kt = Kg + (size_t)kt*64*64;
        const float* Vt = Vg + (size_t)kt*64*64;
        for (int i = tid; i < 1024; i += 256) {
            int r = i >> 4, c4 = (i & 15) << 2;
            float4 kv4 = *(const float4*)(Kt + r*64 + c4);
            uint32_t* dk = sK + r*AST + c4;
            dk[0] = f2t(kv4.x); dk[1] = f2t(kv4.y); dk[2] = f2t(kv4.z); dk[3] = f2t(kv4.w);
            float4 vv4 = *(const float4*)(Vt + r*64 + c4);
            uint32_t* dv = sV + r*AST + c4;
            dv[0] = f2t(vv4.x); dv[1] = f2t(vv4.y); dv[2] = f2t(vv4.z); dv[3] = f2t(vv4.w);
        }
        __syncthreads();

        // ---- S = Q K^T : warp computes 16x64 ----
        float sc[8][4];
        #pragma unroll
        for (int nt = 0; nt < 8; nt++)
            #pragma unroll
            for (int j = 0; j < 4; j++) sc[nt][j] = 0.f;

        #pragma unroll
        for (int kc = 0; kc < 8; kc++) {
            int cidx = kc*8 + tg;
            uint32_t a0 = sQ[r0*AST + cidx];
            uint32_t a1 = sQ[(r0+8)*AST + cidx];
            uint32_t a2 = sQ[r0*AST + cidx + 4];
            uint32_t a3 = sQ[(r0+8)*AST + cidx + 4];
            #pragma unroll
            for (int nt = 0; nt < 8; nt++) {
                uint32_t b0 = sK[(nt*8+g)*AST + cidx];
                uint32_t b1 = sK[(nt*8+g)*AST + cidx + 4];
                mma8(sc[nt], a0, a1, a2, a3, b0, b1);
            }
        }

        // ---- online softmax (rows r0, r0+8; quad-local reduce) ----
        float t0 = -1e30f, t1 = -1e30f;
        #pragma unroll
        for (int nt = 0; nt < 8; nt++) {
            t0 = fmaxf(t0, fmaxf(sc[nt][0], sc[nt][1]));
            t1 = fmaxf(t1, fmaxf(sc[nt][2], sc[nt][3]));
        }
        t0 = fmaxf(t0, __shfl_xor_sync(0xffffffffu, t0, 1));
        t0 = fmaxf(t0, __shfl_xor_sync(0xffffffffu, t0, 2));
        t1 = fmaxf(t1, __shfl_xor_sync(0xffffffffu, t1, 1));
        t1 = fmaxf(t1, __shfl_xor_sync(0xffffffffu, t1, 2));
        float mn0 = fmaxf(m0, t0), mn1 = fmaxf(m1, t1);
        float corr0 = __expf((m0 - mn0) * scale);
        float corr1 = __expf((m1 - mn1) * scale);
        m0 = mn0; m1 = mn1;

        float rs0 = 0.f, rs1 = 0.f;
        #pragma unroll
        for (int nt = 0; nt < 8; nt++) {
            float e0 = __expf((sc[nt][0] - mn0) * scale);
            float e1 = __expf((sc[nt][1] - mn0) * scale);
            float e2 = __expf((sc[nt][2] - mn1) * scale);
            float e3 = __expf((sc[nt][3] - mn1) * scale);
            rs0 += e0 + e1;
            rs1 += e2 + e3;
            int cbase = nt*8 + 2*tg;
            sP[r0*AST + cbase]       = f2t(e0);
            sP[r0*AST + cbase + 1]   = f2t(e1);
            sP[(r0+8)*AST + cbase]     = f2t(e2);
            sP[(r0+8)*AST + cbase + 1] = f2t(e3);
        }
        rs0 += __shfl_xor_sync(0xffffffffu, rs0, 1);
        rs0 += __shfl_xor_sync(0xffffffffu, rs0, 2);
        rs1 += __shfl_xor_sync(0xffffffffu, rs1, 1);
        rs1 += __shfl_xor_sync(0xffffffffu, rs1, 2);
        l0 = l0*corr0 + rs0;
        l1 = l1*corr1 + rs1;
        #pragma unroll
        for (int nt = 0; nt < 8; nt++) {
            o[nt][0] *= corr0; o[nt][1] *= corr0;
            o[nt][2] *= corr1; o[nt][3] *= corr1;
        }
        __syncwarp();   // sP rows of this warp visible to whole warp

        // ---- O += P V ----
        #pragma unroll
        for (int kc = 0; kc < 8; kc++) {
            int cidx = kc*8 + tg;
            uint32_t a0 = sP[r0*AST + cidx];
            uint32_t a1 = sP[(r0+8)*AST + cidx];
            uint32_t a2 = sP[r0*AST + cidx + 4];
            uint32_t a3 = sP[(r0+8)*AST + cidx + 4];
            #pragma unroll
            for (int nt = 0; nt < 8; nt++) {
                uint32_t b0 = sV[cidx*AST + nt*8 + g];
                uint32_t b1 = sV[(cidx+4)*AST + nt*8 + g];
                mma8(o[nt], a0, a1, a2, a3, b0, b1);
            }
        }
    }

    // ---- epilogue: normalize, write (b, s, e) layout ----
    const int b  = bh >> 4, h = bh & 15;
    float inv0 = 1.0f / l0, inv1 = 1.0f / l1;
    int s0 = qt*128 + r0;
    float* out0 = g_att + ((size_t)(b*S + s0))*E + h*64;
    float* out1 = g_att + ((size_t)(b*S + s0 + 8))*E + h*64;
    #pragma unroll
    for (int nt = 0; nt < 8; nt++) {
        int cbase = nt*8 + 2*tg;
        float2 v0 = make_float2(o[nt][0]*inv0, o[nt][1]*inv0);
        float2 v1 = make_float2(o[nt][2]*inv1, o[nt][3]*inv1);
        *(float2*)(out0 + cbase) = v0;
        *(float2*)(out1 + cbase) = v1;
    }
}

// =====================================================================
// Kernel 3: output projection, split-tf32 (3-term, ~fp32 accuracy).
// C[4096,1024] = A @ Wo^T + bo. Tile 128x128 per block, ktile 32.
// 8 warps: warp (w&3) -> 32 rows, (w>>2) -> 64 cols.
// stride 36 -> conflict-free fragment loads ((4g + c) % 32 distinct).
// =====================================================================
#define OST 36
#define OPROJ_SMEM (4 * 128 * OST * 4)

__global__ void __launch_bounds__(256, 2) oproj_kernel(const float* __restrict__ Wo,
                                                       const float* __restrict__ bo,
                                                       float* __restrict__ out) {
    extern __shared__ uint32_t smu[];
    uint32_t* sAh = smu;                  // [128][36]
    uint32_t* sAl = sAh + 128*OST;
    uint32_t* sWh = sAl + 128*OST;
    uint32_t* sWl = sWh + 128*OST;

    const int tid  = threadIdx.x;
    const int w    = tid >> 5;
    const int lane = tid & 31;
    const int g    = lane >> 2;
    const int tg   = lane & 3;
    const int m0   = (w & 3) * 32;        // warp row base (local)
    const int n0   = (w >> 2) * 64;       // warp col base (local)
    const int mg   = blockIdx.y * 128;
    const int ng   = blockIdx.x * 128;

    float acc[2][8][4];
    #pragma unroll
    for (int mi = 0; mi < 2; mi++)
        #pragma unroll
        for (int nt = 0; nt < 8; nt++)
            #pragma unroll
            for (int j = 0; j < 4; j++) acc[mi][nt][j] = 0.f;

    for (int kt = 0; kt < E/32; kt++) {
        __syncthreads();
        for (int i = tid; i < 1024; i += 256) {
            int r = i >> 3, c4 = (i & 7) << 2;
            float4 a = *(const float4*)(g_att + (size_t)(mg + r)*E + kt*32 + c4);
            float4 ww = *(const float4*)(Wo   + (size_t)(ng + r)*E + kt*32 + c4);
            uint32_t* pah = sAh + r*OST + c4;
            uint32_t* pal = sAl + r*OST + c4;
            uint32_t* pwh = sWh + r*OST + c4;
            uint32_t* pwl = sWl + r*OST + c4;
            float av[4] = {a.x, a.y, a.z, a.w};
            float wv[4] = {ww.x, ww.y, ww.z, ww.w};
            #pragma unroll
            for (int j = 0; j < 4; j++) {
                uint32_t ah = f2t(av[j]);
                pah[j] = ah;
                pal[j] = f2t(av[j] - __uint_as_float(ah));
                uint32_t wh = f2t(wv[j]);
                pwh[j] = wh;
                pwl[j] = f2t(wv[j] - __uint_as_float(wh));
            }
        }
        __syncthreads();

        #pragma unroll
        for (int kc = 0; kc < 4; kc++) {
            int cidx = kc*8 + tg;
            uint32_t ah[2][4], al[2][4];
            #pragma unroll
            for (int mi = 0; mi < 2; mi++) {
                int rr = m0 + 16*mi + g;
                ah[mi][0] = sAh[rr*OST + cidx];
                ah[mi][1] = sAh[(rr+8)*OST + cidx];
                ah[mi][2] = sAh[rr*OST + cidx + 4];
                ah[mi][3] = sAh[(rr+8)*OST + cidx + 4];
                al[mi][0] = sAl[rr*OST + cidx];
                al[mi][1] = sAl[(rr+8)*OST + cidx];
                al[mi][2] = sAl[rr*OST + cidx + 4];
                al[mi][3] = sAl[(rr+8)*OST + cidx + 4];
            }
            #pragma unroll
            for (int nt = 0; nt < 8; nt++) {
                int nr = n0 + nt*8 + g;
                uint32_t b0h = sWh[nr*OST + cidx];
                uint32_t b1h = sWh[nr*OST + cidx + 4];
                uint32_t b0l = sWl[nr*OST + cidx];
                uint32_t b1l = sWl[nr*OST + cidx + 4];
                #pragma unroll
                for (int mi = 0; mi < 2; mi++) {
                    mma8(acc[mi][nt], ah[mi][0], ah[mi][1], ah[mi][2], ah[mi][3], b0h, b1h);
                    mma8(acc[mi][nt], ah[mi][0], ah[mi][1], ah[mi][2], ah[mi][3], b0l, b1l);
                    mma8(acc[mi][nt], al[mi][0], al[mi][1], al[mi][2], al[mi][3], b0h, b1h);
                }
            }
        }
    }

    // epilogue with bias
    #pragma unroll
    for (int mi = 0; mi < 2; mi++) {
        int row = mg + m0 + 16*mi + g;
        #pragma unroll
        for (int nt = 0; nt < 8; nt++) {
            int col = ng + n0 + nt*8 + 2*tg;
            float2 bb = *(const float2*)(bo + col);
            float2 v0 = make_float2(acc[mi][nt][0] + bb.x, acc[mi][nt][1] + bb.y);
            float2 v1 = make_float2(acc[mi][nt][2] + bb.x, acc[mi][nt][3] + bb.y);
            *(float2*)(out + (size_t)row*E + col)       = v0;
            *(float2*)(out + (size_t)(row+8)*E + col)   = v1;
        }
    }
}

// =====================================================================
extern "C" void kernel_launch(void* const* d_in, const int* in_sizes, int n_in,
                              void* d_out, int out_size) {
    const float* x  = (const float*)d_in[0];
    const float* Wq = (const float*)d_in[1];
    const float* Wk = (const float*)d_in[2];
    const float* Wv = (const float*)d_in[3];
    const float* Wo = (const float*)d_in[4];
    const float* bo = (const float*)d_in[5];
    float* out = (float*)d_out;

    cudaFuncSetAttribute(qkv_kernel,   cudaFuncAttributeMaxDynamicSharedMemorySize, QKV_SMEM);
    cudaFuncSetAttribute(attn_kernel,  cudaFuncAttributeMaxDynamicSharedMemorySize, ATTN_SMEM);
    cudaFuncSetAttribute(oproj_kernel, cudaFuncAttributeMaxDynamicSharedMemorySize, OPROJ_SMEM);

    qkv_kernel<<<NROW / K1_ROWS, 256, QKV_SMEM>>>(x, Wq, Wk, Wv);
    attn_kernel<<<dim3(S/128, BH), 256, ATTN_SMEM>>>();
    oproj_kernel<<<dim3(E/128, (B*S)/128), 256, OPROJ_SMEM>>>(Wo, bo, out);
}

// round 4
// speedup vs baseline: 2.6954x; 1.3657x over previous
#include <cuda_runtime.h>
#include <cuda_bf16.h>
#include <cstdint>

#define B 2
#define S 2048
#define E 1024
#define H 16
#define D 64
#define BH (B*H)            // 32
#define NROW (B*S*H)        // 65536

// Scratch (allocation-free rule: __device__ globals)
__device__ float g_q[B*H*S*D];
__device__ float g_k[B*H*S*D];
__device__ float g_v[B*H*S*D];
__device__ float g_att[B*S*E];

// ---------------------------------------------------------------------
// tf32 helpers
// ---------------------------------------------------------------------
__device__ __forceinline__ uint32_t f2t(float f) {
    uint32_t u;
    asm("cvt.rna.tf32.f32 %0, %1;" : "=r"(u) : "f"(f));
    return u;
}

__device__ __forceinline__ void mma8(float* c, uint32_t a0, uint32_t a1,
                                     uint32_t a2, uint32_t a3,
                                     uint32_t b0, uint32_t b1) {
    asm volatile(
        "mma.sync.aligned.m16n8k8.row.col.f32.tf32.tf32.f32 "
        "{%0,%1,%2,%3},{%4,%5,%6,%7},{%8,%9},{%0,%1,%2,%3};"
        : "+f"(c[0]), "+f"(c[1]), "+f"(c[2]), "+f"(c[3])
        : "r"(a0), "r"(a1), "r"(a2), "r"(a3), "r"(b0), "r"(b1));
}

// =====================================================================
// Kernel 1: QKV projection, split-tf32 MMA (fp32-accurate, memory-bound)
// 256 threads (8 warps). Block = 128 x-rows. N = 192 (q|k|v).
// warp w owns rows [16w, 16w+16). 3-term split: ah*bh + ah*bl + al*bh.
// =====================================================================
#define QST 68
#define QKV_SMEM ((128*QST*2 + 192*QST*2) * 4)   // 174,080 B

__global__ void __launch_bounds__(256, 1) qkv_kernel(const float* __restrict__ x,
                                                     const float* __restrict__ Wq,
                                                     const float* __restrict__ Wk,
                                                     const float* __restrict__ Wv) {
    extern __shared__ uint32_t smu[];
    uint32_t* sXh = smu;                 // [128][QST]
    uint32_t* sXl = sXh + 128*QST;
    uint32_t* sWh = sXl + 128*QST;       // [192][QST]  rows: 0..63 Wq, 64..127 Wk, 128..191 Wv
    uint32_t* sWl = sWh + 192*QST;

    const int tid  = threadIdx.x;
    const int w    = tid >> 5;
    const int lane = tid & 31;
    const int g    = lane >> 2;
    const int tg   = lane & 3;
    const int g0   = blockIdx.x * 128;

    // Stage weights hi/lo
    for (int i = tid; i < 3072; i += 256) {
        int m = i >> 10, r = (i >> 4) & 63, c4 = (i & 15) << 2;
        const float* Ws = (m == 0) ? Wq : (m == 1) ? Wk : Wv;
        float4 v = *(const float4*)(Ws + r*64 + c4);
        uint32_t* ph = sWh + (m*64 + r)*QST + c4;
        uint32_t* pl = sWl + (m*64 + r)*QST + c4;
        float vv[4] = {v.x, v.y, v.z, v.w};
        #pragma unroll
        for (int j = 0; j < 4; j++) {
            uint32_t h = f2t(vv[j]);
            ph[j] = h;
            pl[j] = f2t(vv[j] - __uint_as_float(h));
        }
    }
    // Stage x tile hi/lo
    for (int i = tid; i < 2048; i += 256) {
        int r = i >> 4, c4 = (i & 15) << 2;
        float4 v = *(const float4*)(x + (size_t)(g0 + r)*64 + c4);
        uint32_t* ph = sXh + r*QST + c4;
        uint32_t* pl = sXl + r*QST + c4;
        float vv[4] = {v.x, v.y, v.z, v.w};
        #pragma unroll
        for (int j = 0; j < 4; j++) {
            uint32_t h = f2t(vv[j]);
            ph[j] = h;
            pl[j] = f2t(vv[j] - __uint_as_float(h));
        }
    }
    __syncthreads();

    float acc[24][4];
    #pragma unroll
    for (int nt = 0; nt < 24; nt++)
        #pragma unroll
        for (int j = 0; j < 4; j++) acc[nt][j] = 0.f;

    const int r0 = 16*w + g;
    #pragma unroll
    for (int kc = 0; kc < 8; kc++) {
        int cidx = kc*8 + tg;
        uint32_t ah0 = sXh[r0*QST + cidx],     ah1 = sXh[(r0+8)*QST + cidx];
        uint32_t ah2 = sXh[r0*QST + cidx + 4], ah3 = sXh[(r0+8)*QST + cidx + 4];
        uint32_t al0 = sXl[r0*QST + cidx],     al1 = sXl[(r0+8)*QST + cidx];
        uint32_t al2 = sXl[r0*QST + cidx + 4], al3 = sXl[(r0+8)*QST + cidx + 4];
        #pragma unroll
        for (int nt = 0; nt < 24; nt++) {
            int nr = nt*8 + g;
            uint32_t bh0 = sWh[nr*QST + cidx], bh1 = sWh[nr*QST + cidx + 4];
            uint32_t bl0 = sWl[nr*QST + cidx], bl1 = sWl[nr*QST + cidx + 4];
            mma8(acc[nt], ah0, ah1, ah2, ah3, bh0, bh1);
            mma8(acc[nt], ah0, ah1, ah2, ah3, bl0, bl1);
            mma8(acc[nt], al0, al1, al2, al3, bh0, bh1);
        }
    }

    // Store: row gr -> (b,s,h); out layout (b,h,s,d)
    int gr0 = g0 + r0, gr1 = gr0 + 8;
    int b0 = gr0 >> 15, s0 = (gr0 & 32767) >> 4, h0 = gr0 & 15;
    int b1 = gr1 >> 15, s1 = (gr1 & 32767) >> 4, h1 = gr1 & 15;
    size_t orow0 = ((size_t)(b0*H + h0)*S + s0) * 64;
    size_t orow1 = ((size_t)(b1*H + h1)*S + s1) * 64;
    #pragma unroll
    for (int nt = 0; nt < 24; nt++) {
        int mat = nt >> 3;
        int e   = (nt & 7)*8 + 2*tg;
        float* dst = (mat == 0) ? g_q : (mat == 1) ? g_k : g_v;
        *(float2*)(dst + orow0 + e) = make_float2(acc[nt][0], acc[nt][1]);
        *(float2*)(dst + orow1 + e) = make_float2(acc[nt][2], acc[nt][3]);
    }
}

// =====================================================================
// Kernel 2: flash attention, tf32 mma. Br=128, Bc=64.
// 4 warps / 128 threads; warp w owns 32 q-rows (2 m16 tiles) -> B-frag
// reuse halves LDS per mma. sV stride 72 -> conflict-free PV B loads.
// grid (S/128, B*H), 2 CTAs/SM.
// =====================================================================
#define AST 68
#define VST 72
#define ATTN_SMEM ((128*AST + 64*AST + 64*VST + 128*AST) * 4)   // 105,472 B

__global__ void __launch_bounds__(128, 2) attn_kernel() {
    extern __shared__ uint32_t smu[];
    uint32_t* sQ = smu;              // [128][AST] tf32
    uint32_t* sK = sQ + 128*AST;     // [64][AST]  tf32  [kv][d]
    uint32_t* sV = sK + 64*AST;      // [64][VST]  tf32  [kv][d]
    uint32_t* sP = sV + 64*VST;      // [128][AST] tf32

    const int tid  = threadIdx.x;
    const int w    = tid >> 5;
    const int lane = tid & 31;
    const int g    = lane >> 2;
    const int tg   = lane & 3;
    const int qt   = blockIdx.x;
    const int bh   = blockIdx.y;

    const float* Qg = g_q + (size_t)bh*S*D + (size_t)qt*128*D;
    const float* Kg = g_k + (size_t)bh*S*D;
    const float* Vg = g_v + (size_t)bh*S*D;

    // Load + convert Q tile (128x64)
    for (int i = tid; i < 2048; i += 128) {
        int r = i >> 4, c4 = (i & 15) << 2;
        float4 v = *(const float4*)(Qg + r*64 + c4);
        uint32_t* dst = sQ + r*AST + c4;
        dst[0] = f2t(v.x); dst[1] = f2t(v.y); dst[2] = f2t(v.z); dst[3] = f2t(v.w);
    }

    const int rw = 32*w;             // warp row base
    float m[2][2], l[2][2];
    float o[2][8][4];
    #pragma unroll
    for (int mi = 0; mi < 2; mi++) {
        m[mi][0] = m[mi][1] = -1e30f;
        l[mi][0] = l[mi][1] = 0.f;
        #pragma unroll
        for (int nt = 0; nt < 8; nt++)
            #pragma unroll
            for (int j = 0; j < 4; j++) o[mi][nt][j] = 0.f;
    }

    const float scale = 0.125f;      // 1/sqrt(64)

    for (int kt = 0; kt < S/64; kt++) {
        __syncthreads();
        const float* Kt = Kg + (size_t)kt*64*64;
        const float* Vt = Vg + (size_t)kt*64*64;
        for (int i = tid; i < 1024; i += 128) {
            int r = i >> 4, c4 = (i & 15) << 2;
            float4 kv4 = *(const float4*)(Kt + r*64 + c4);
            uint32_t* dk = sK + r*AST + c4;
            dk[0] = f2t(kv4.x); dk[1] = f2t(kv4.y); dk[2] = f2t(kv4.z); dk[3] = f2t(kv4.w);
            float4 vv4 = *(const float4*)(Vt + r*64 + c4);
            uint32_t* dv = sV + r*VST + c4;
            dv[0] = f2t(vv4.x); dv[1] = f2t(vv4.y); dv[2] = f2t(vv4.z); dv[3] = f2t(vv4.w);
        }
        __syncthreads();

        // ---- S = Q K^T : warp computes 32x64 (2 m-tiles x 8 n-tiles) ----
        float sc[2][8][4];
        #pragma unroll
        for (int mi = 0; mi < 2; mi++)
            #pragma unroll
            for (int nt = 0; nt < 8; nt++)
                #pragma unroll
                for (int j = 0; j < 4; j++) sc[mi][nt][j] = 0.f;

        #pragma unroll
        for (int kc = 0; kc < 8; kc++) {
            int cidx = kc*8 + tg;
            uint32_t a0[2], a1[2], a2[2], a3[2];
            #pragma unroll
            for (int mi = 0; mi < 2; mi++) {
                int r = rw + 16*mi + g;
                a0[mi] = sQ[r*AST + cidx];
                a1[mi] = sQ[(r+8)*AST + cidx];
                a2[mi] = sQ[r*AST + cidx + 4];
                a3[mi] = sQ[(r+8)*AST + cidx + 4];
            }
            #pragma unroll
            for (int nt = 0; nt < 8; nt++) {
                uint32_t b0 = sK[(nt*8+g)*AST + cidx];
                uint32_t b1 = sK[(nt*8+g)*AST + cidx + 4];
                mma8(sc[0][nt], a0[0], a1[0], a2[0], a3[0], b0, b1);
                mma8(sc[1][nt], a0[1], a1[1], a2[1], a3[1], b0, b1);
            }
        }

        // ---- online softmax per m-tile ----
        #pragma unroll
        for (int mi = 0; mi < 2; mi++) {
            float t0 = -1e30f, t1 = -1e30f;
            #pragma unroll
            for (int nt = 0; nt < 8; nt++) {
                t0 = fmaxf(t0, fmaxf(sc[mi][nt][0], sc[mi][nt][1]));
                t1 = fmaxf(t1, fmaxf(sc[mi][nt][2], sc[mi][nt][3]));
            }
            t0 = fmaxf(t0, __shfl_xor_sync(0xffffffffu, t0, 1));
            t0 = fmaxf(t0, __shfl_xor_sync(0xffffffffu, t0, 2));
            t1 = fmaxf(t1, __shfl_xor_sync(0xffffffffu, t1, 1));
            t1 = fmaxf(t1, __shfl_xor_sync(0xffffffffu, t1, 2));
            float mn0 = fmaxf(m[mi][0], t0), mn1 = fmaxf(m[mi][1], t1);
            float corr0 = __expf((m[mi][0] - mn0) * scale);
            float corr1 = __expf((m[mi][1] - mn1) * scale);
            m[mi][0] = mn0; m[mi][1] = mn1;

            int rr = rw + 16*mi + g;
            float rs0 = 0.f, rs1 = 0.f;
            #pragma unroll
            for (int nt = 0; nt < 8; nt++) {
                float e0 = __expf((sc[mi][nt][0] - mn0) * scale);
                float e1 = __expf((sc[mi][nt][1] - mn0) * scale);
                float e2 = __expf((sc[mi][nt][2] - mn1) * scale);
                float e3 = __expf((sc[mi][nt][3] - mn1) * scale);
                rs0 += e0 + e1;
                rs1 += e2 + e3;
                int cb = nt*8 + 2*tg;
                sP[rr*AST + cb]         = f2t(e0);
                sP[rr*AST + cb + 1]     = f2t(e1);
                sP[(rr+8)*AST + cb]     = f2t(e2);
                sP[(rr+8)*AST + cb + 1] = f2t(e3);
            }
            rs0 += __shfl_xor_sync(0xffffffffu, rs0, 1);
            rs0 += __shfl_xor_sync(0xffffffffu, rs0, 2);
            rs1 += __shfl_xor_sync(0xffffffffu, rs1, 1);
            rs1 += __shfl_xor_sync(0xffffffffu, rs1, 2);
            l[mi][0] = l[mi][0]*corr0 + rs0;
            l[mi][1] = l[mi][1]*corr1 + rs1;
            #pragma unroll
            for (int nt = 0; nt < 8; nt++) {
                o[mi][nt][0] *= corr0; o[mi][nt][1] *= corr0;
                o[mi][nt][2] *= corr1; o[mi][nt][3] *= corr1;
            }
        }
        __syncwarp();

        // ---- O += P V ----
        #pragma unroll
        for (int kc = 0; kc < 8; kc++) {
            int cidx = kc*8 + tg;
            uint32_t a0[2], a1[2], a2[2], a3[2];
            #pragma unroll
            for (int mi = 0; mi < 2; mi++) {
                int r = rw + 16*mi + g;
                a0[mi] = sP[r*AST + cidx];
                a1[mi] = sP[(r+8)*AST + cidx];
                a2[mi] = sP[r*AST + cidx + 4];
                a3[mi] = sP[(r+8)*AST + cidx + 4];
            }
            #pragma unroll
            for (int nt = 0; nt < 8; nt++) {
                uint32_t b0 = sV[cidx*VST + nt*8 + g];
                uint32_t b1 = sV[(cidx+4)*VST + nt*8 + g];
                mma8(o[0][nt], a0[0], a1[0], a2[0], a3[0], b0, b1);
                mma8(o[1][nt], a0[1], a1[1], a2[1], a3[1], b0, b1);
            }
        }
    }

    // ---- epilogue: normalize, write (b, s, e) layout ----
    const int b = bh >> 4, h = bh & 15;
    #pragma unroll
    for (int mi = 0; mi < 2; mi++) {
        int s0 = qt*128 + rw + 16*mi + g;
        float inv0 = 1.0f / l[mi][0], inv1 = 1.0f / l[mi][1];
        float* out0 = g_att + ((size_t)(b*S + s0))*E + h*64;
        float* out1 = g_att + ((size_t)(b*S + s0 + 8))*E + h*64;
        #pragma unroll
        for (int nt = 0; nt < 8; nt++) {
            int cb = nt*8 + 2*tg;
            *(float2*)(out0 + cb) = make_float2(o[mi][nt][0]*inv0, o[mi][nt][1]*inv0);
            *(float2*)(out1 + cb) = make_float2(o[mi][nt][2]*inv1, o[mi][nt][3]*inv1);
        }
    }
}

// =====================================================================
// Kernel 3: output projection, split-tf32 (3-term, ~fp32 accuracy).
// C[4096,1024] = A @ Wo^T + bo. Tile 128x128 per block, ktile 32.
// =====================================================================
#define OST 36
#define OPROJ_SMEM (4 * 128 * OST * 4)

__global__ void __launch_bounds__(256, 2) oproj_kernel(const float* __restrict__ Wo,
                                                       const float* __restrict__ bo,
                                                       float* __restrict__ out) {
    extern __shared__ uint32_t smu[];
    uint32_t* sAh = smu;                  // [128][36]
    uint32_t* sAl = sAh + 128*OST;
    uint32_t* sWh = sAl + 128*OST;
    uint32_t* sWl = sWh + 128*OST;

    const int tid  = threadIdx.x;
    const int w    = tid >> 5;
    const int lane = tid & 31;
    const int g    = lane >> 2;
    const int tg   = lane & 3;
    const int m0   = (w & 3) * 32;
    const int n0   = (w >> 2) * 64;
    const int mg   = blockIdx.y * 128;
    const int ng   = blockIdx.x * 128;

    float acc[2][8][4];
    #pragma unroll
    for (int mi = 0; mi < 2; mi++)
        #pragma unroll
        for (int nt = 0; nt < 8; nt++)
            #pragma unroll
            for (int j = 0; j < 4; j++) acc[mi][nt][j] = 0.f;

    for (int kt = 0; kt < E/32; kt++) {
        __syncthreads();
        for (int i = tid; i < 1024; i += 256) {
            int r = i >> 3, c4 = (i & 7) << 2;
            float4 a  = *(const float4*)(g_att + (size_t)(mg + r)*E + kt*32 + c4);
            float4 ww = *(const float4*)(Wo    + (size_t)(ng + r)*E + kt*32 + c4);
            uint32_t* pah = sAh + r*OST + c4;
            uint32_t* pal = sAl + r*OST + c4;
            uint32_t* pwh = sWh + r*OST + c4;
            uint32_t* pwl = sWl + r*OST + c4;
            float av[4] = {a.x, a.y, a.z, a.w};
            float wv[4] = {ww.x, ww.y, ww.z, ww.w};
            #pragma unroll
            for (int j = 0; j < 4; j++) {
                uint32_t ah = f2t(av[j]);
                pah[j] = ah;
                pal[j] = f2t(av[j] - __uint_as_float(ah));
                uint32_t wh = f2t(wv[j]);
                pwh[j] = wh;
                pwl[j] = f2t(wv[j] - __uint_as_float(wh));
            }
        }
        __syncthreads();

        #pragma unroll
        for (int kc = 0; kc < 4; kc++) {
            int cidx = kc*8 + tg;
            uint32_t ah[2][4], al[2][4];
            #pragma unroll
            for (int mi = 0; mi < 2; mi++) {
                int rr = m0 + 16*mi + g;
                ah[mi][0] = sAh[rr*OST + cidx];
                ah[mi][1] = sAh[(rr+8)*OST + cidx];
                ah[mi][2] = sAh[rr*OST + cidx + 4];
                ah[mi][3] = sAh[(rr+8)*OST + cidx + 4];
                al[mi][0] = sAl[rr*OST + cidx];
                al[mi][1] = sAl[(rr+8)*OST + cidx];
                al[mi][2] = sAl[rr*OST + cidx + 4];
                al[mi][3] = sAl[(rr+8)*OST + cidx + 4];
            }
            #pragma unroll
            for (int nt = 0; nt < 8; nt++) {
                int nr = n0 + nt*8 + g;
                uint32_t b0h = sWh[nr*OST + cidx];
                uint32_t b1h = sWh[nr*OST + cidx + 4];
                uint32_t b0l = sWl[nr*OST + cidx];
                uint32_t b1l = sWl[nr*OST + cidx + 4];
                #pragma unroll
                for (int mi = 0; mi < 2; mi++) {
                    mma8(acc[mi][nt], ah[mi][0], ah[mi][1], ah[mi][2], ah[mi][3], b0h, b1h);
                    mma8(acc[mi][nt], ah[mi][0], ah[mi][1], ah[mi][2], ah[mi][3], b0l, b1l);
                    mma8(acc[mi][nt], al[mi][0], al[mi][1], al[mi][2], al[mi][3], b0h, b1h);
                }
            }
        }
    }

    #pragma unroll
    for (int mi = 0; mi < 2; mi++) {
        int row = mg + m0 + 16*mi + g;
        #pragma unroll
        for (int nt = 0; nt < 8; nt++) {
            int col = ng + n0 + nt*8 + 2*tg;
            float2 bb = *(const float2*)(bo + col);
            *(float2*)(out + (size_t)row*E + col)
                = make_float2(acc[mi][nt][0] + bb.x, acc[mi][nt][1] + bb.y);
            *(float2*)(out + (size_t)(row+8)*E + col)
                = make_float2(acc[mi][nt][2] + bb.x, acc[mi][nt][3] + bb.y);
        }
    }
}

// =====================================================================
extern "C" void kernel_launch(void* const* d_in, const int* in_sizes, int n_in,
                              void* d_out, int out_size) {
    const float* x  = (const float*)d_in[0];
    const float* Wq = (const float*)d_in[1];
    const float* Wk = (const float*)d_in[2];
    const float* Wv = (const float*)d_in[3];
    const float* Wo = (const float*)d_in[4];
    const float* bo = (const float*)d_in[5];
    float* out = (float*)d_out;

    cudaFuncSetAttribute(qkv_kernel,   cudaFuncAttributeMaxDynamicSharedMemorySize, QKV_SMEM);
    cudaFuncSetAttribute(attn_kernel,  cudaFuncAttributeMaxDynamicSharedMemorySize, ATTN_SMEM);
    cudaFuncSetAttribute(oproj_kernel, cudaFuncAttributeMaxDynamicSharedMemorySize, OPROJ_SMEM);

    qkv_kernel<<<NROW / 128, 256, QKV_SMEM>>>(x, Wq, Wk, Wv);
    attn_kernel<<<dim3(S/128, BH), 128, ATTN_SMEM>>>();
    oproj_kernel<<<dim3(E/128, (B*S)/128), 256, OPROJ_SMEM>>>(Wo, bo, out);
}

// round 5
// speedup vs baseline: 3.5907x; 1.3321x over previous
#include <cuda_runtime.h>
#include <cuda_bf16.h>
#include <cstdint>

#define B 2
#define S 2048
#define E 1024
#define H 16
#define D 64
#define BH (B*H)            // 32
#define NROW (B*S*H)        // 65536

// Scratch (allocation-free rule: __device__ globals)
__device__ float g_q[B*H*S*D];
__device__ float g_k[B*H*S*D];
__device__ float g_v[B*H*S*D];
__device__ float g_att[B*S*E];

// ---------------------------------------------------------------------
// helpers
// ---------------------------------------------------------------------
__device__ __forceinline__ uint32_t f2t(float f) {
    uint32_t u;
    asm("cvt.rna.tf32.f32 %0, %1;" : "=r"(u) : "f"(f));
    return u;
}

__device__ __forceinline__ uint32_t fpack_bf16(float lo, float hi) {
    __nv_bfloat162 h = __floats2bfloat162_rn(lo, hi);   // .x = lo (low 16 bits)
    return *(uint32_t*)&h;
}

// tf32 m16n8k8
__device__ __forceinline__ void mma8(float* c, uint32_t a0, uint32_t a1,
                                     uint32_t a2, uint32_t a3,
                                     uint32_t b0, uint32_t b1) {
    asm volatile(
        "mma.sync.aligned.m16n8k8.row.col.f32.tf32.tf32.f32 "
        "{%0,%1,%2,%3},{%4,%5,%6,%7},{%8,%9},{%0,%1,%2,%3};"
        : "+f"(c[0]), "+f"(c[1]), "+f"(c[2]), "+f"(c[3])
        : "r"(a0), "r"(a1), "r"(a2), "r"(a3), "r"(b0), "r"(b1));
}

// bf16 m16n8k16
__device__ __forceinline__ void mma16(float* c, uint32_t a0, uint32_t a1,
                                      uint32_t a2, uint32_t a3,
                                      uint32_t b0, uint32_t b1) {
    asm volatile(
        "mma.sync.aligned.m16n8k16.row.col.f32.bf16.bf16.f32 "
        "{%0,%1,%2,%3},{%4,%5,%6,%7},{%8,%9},{%0,%1,%2,%3};"
        : "+f"(c[0]), "+f"(c[1]), "+f"(c[2]), "+f"(c[3])
        : "r"(a0), "r"(a1), "r"(a2), "r"(a3), "r"(b0), "r"(b1));
}

// split a float into bf16 hi/lo
__device__ __forceinline__ void bsplit(float f, float& hi, float& lo) {
    __nv_bfloat16 h = __float2bfloat16_rn(f);
    hi = __bfloat162float(h);
    lo = f - hi;
}

// =====================================================================
// Kernel 1: QKV projection, split-bf16 (3-term) MMA.
// 256 threads, 8 warps; block = 128 x-rows; N = 192 (q|k|v).
// smem layout: packed bf16x2 pairs along k, stride 36 words.
// =====================================================================
#define QSTB 36
#define QKV_SMEM ((128*QSTB*2 + 192*QSTB*2) * 4)   // 92,160 B

__global__ void __launch_bounds__(256, 1) qkv_kernel(const float* __restrict__ x,
                                                     const float* __restrict__ Wq,
                                                     const float* __restrict__ Wk,
                                                     const float* __restrict__ Wv) {
    extern __shared__ uint32_t smu[];
    uint32_t* sXh = smu;                  // [128][QSTB]
    uint32_t* sXl = sXh + 128*QSTB;
    uint32_t* sWh = sXl + 128*QSTB;       // [192][QSTB]
    uint32_t* sWl = sWh + 192*QSTB;

    const int tid  = threadIdx.x;
    const int w    = tid >> 5;
    const int lane = tid & 31;
    const int g    = lane >> 2;
    const int tg   = lane & 3;
    const int g0   = blockIdx.x * 128;

    // Stage weights hi/lo (packed pairs)
    for (int i = tid; i < 3072; i += 256) {
        int m = i >> 10, r = (i >> 4) & 63, c4 = (i & 15) << 2;
        const float* Ws = (m == 0) ? Wq : (m == 1) ? Wk : Wv;
        float4 v = *(const float4*)(Ws + r*64 + c4);
        float h0,l0,h1,l1,h2,l2,h3,l3;
        bsplit(v.x,h0,l0); bsplit(v.y,h1,l1); bsplit(v.z,h2,l2); bsplit(v.w,h3,l3);
        int base = (m*64 + r)*QSTB + (c4 >> 1);
        sWh[base]   = fpack_bf16(h0, h1);
        sWh[base+1] = fpack_bf16(h2, h3);
        sWl[base]   = fpack_bf16(l0, l1);
        sWl[base+1] = fpack_bf16(l2, l3);
    }
    // Stage x hi/lo
    for (int i = tid; i < 2048; i += 256) {
        int r = i >> 4, c4 = (i & 15) << 2;
        float4 v = *(const float4*)(x + (size_t)(g0 + r)*64 + c4);
        float h0,l0,h1,l1,h2,l2,h3,l3;
        bsplit(v.x,h0,l0); bsplit(v.y,h1,l1); bsplit(v.z,h2,l2); bsplit(v.w,h3,l3);
        int base = r*QSTB + (c4 >> 1);
        sXh[base]   = fpack_bf16(h0, h1);
        sXh[base+1] = fpack_bf16(h2, h3);
        sXl[base]   = fpack_bf16(l0, l1);
        sXl[base+1] = fpack_bf16(l2, l3);
    }
    __syncthreads();

    float acc[24][4];
    #pragma unroll
    for (int nt = 0; nt < 24; nt++)
        #pragma unroll
        for (int j = 0; j < 4; j++) acc[nt][j] = 0.f;

    const int r0 = 16*w + g;
    #pragma unroll
    for (int kc = 0; kc < 4; kc++) {           // 4 chunks of k16
        int cidx = kc*8 + tg;
        uint32_t ah0 = sXh[r0*QSTB + cidx],     ah1 = sXh[(r0+8)*QSTB + cidx];
        uint32_t ah2 = sXh[r0*QSTB + cidx + 4], ah3 = sXh[(r0+8)*QSTB + cidx + 4];
        uint32_t al0 = sXl[r0*QSTB + cidx],     al1 = sXl[(r0+8)*QSTB + cidx];
        uint32_t al2 = sXl[r0*QSTB + cidx + 4], al3 = sXl[(r0+8)*QSTB + cidx + 4];
        #pragma unroll
        for (int nt = 0; nt < 24; nt++) {
            int nr = nt*8 + g;
            uint32_t bh0 = sWh[nr*QSTB + cidx], bh1 = sWh[nr*QSTB + cidx + 4];
            uint32_t bl0 = sWl[nr*QSTB + cidx], bl1 = sWl[nr*QSTB + cidx + 4];
            mma16(acc[nt], ah0, ah1, ah2, ah3, bh0, bh1);
            mma16(acc[nt], ah0, ah1, ah2, ah3, bl0, bl1);
            mma16(acc[nt], al0, al1, al2, al3, bh0, bh1);
        }
    }

    // Store: row gr -> (b,s,h); out layout (b,h,s,d)
    int gr0 = g0 + r0, gr1 = gr0 + 8;
    int b0 = gr0 >> 15, s0 = (gr0 & 32767) >> 4, h0 = gr0 & 15;
    int b1 = gr1 >> 15, s1 = (gr1 & 32767) >> 4, h1 = gr1 & 15;
    size_t orow0 = ((size_t)(b0*H + h0)*S + s0) * 64;
    size_t orow1 = ((size_t)(b1*H + h1)*S + s1) * 64;
    #pragma unroll
    for (int nt = 0; nt < 24; nt++) {
        int mat = nt >> 3;
        int e   = (nt & 7)*8 + 2*tg;
        float* dst = (mat == 0) ? g_q : (mat == 1) ? g_k : g_v;
        *(float2*)(dst + orow0 + e) = make_float2(acc[nt][0], acc[nt][1]);
        *(float2*)(dst + orow1 + e) = make_float2(acc[nt][2], acc[nt][3]);
    }
}

// =====================================================================
// Kernel 2: flash attention. QK^T in tf32 (m16n8k8), PV in bf16
// (m16n8k16) with A-fragments straight from registers (no sP).
// Br=128, Bc=64, 4 warps; warp owns 32 q-rows. Q pre-scaled by 1/8.
// =====================================================================
#define AST 68
#define VSTB 72
#define ATTN_SMEM ((128*AST + 64*AST + 32*VSTB) * 4)   // 61,440 B

__global__ void __launch_bounds__(128, 2) attn_kernel() {
    extern __shared__ uint32_t smu[];
    uint32_t* sQ  = smu;               // [128][AST]  tf32 (pre-scaled)
    uint32_t* sK  = sQ + 128*AST;      // [64][AST]   tf32 [kv][d]
    uint32_t* sVb = sK + 64*AST;       // [32][VSTB]  bf16x2 pairs [kv/2][d]

    const int tid  = threadIdx.x;
    const int w    = tid >> 5;
    const int lane = tid & 31;
    const int g    = lane >> 2;
    const int tg   = lane & 3;
    const int qt   = blockIdx.x;
    const int bh   = blockIdx.y;

    const float* Qg = g_q + (size_t)bh*S*D + (size_t)qt*128*D;
    const float* Kg = g_k + (size_t)bh*S*D;
    const float* Vg = g_v + (size_t)bh*S*D;

    // Load + convert Q tile (128x64), pre-scaled by 1/8 (exact)
    for (int i = tid; i < 2048; i += 128) {
        int r = i >> 4, c4 = (i & 15) << 2;
        float4 v = *(const float4*)(Qg + r*64 + c4);
        uint32_t* dst = sQ + r*AST + c4;
        dst[0] = f2t(v.x*0.125f); dst[1] = f2t(v.y*0.125f);
        dst[2] = f2t(v.z*0.125f); dst[3] = f2t(v.w*0.125f);
    }

    const int rw = 32*w;
    float m[2][2], l[2][2];
    float o[2][8][4];
    #pragma unroll
    for (int mi = 0; mi < 2; mi++) {
        m[mi][0] = m[mi][1] = -1e30f;
        l[mi][0] = l[mi][1] = 0.f;
        #pragma unroll
        for (int nt = 0; nt < 8; nt++)
            #pragma unroll
            for (int j = 0; j < 4; j++) o[mi][nt][j] = 0.f;
    }

    for (int kt = 0; kt < S/64; kt++) {
        __syncthreads();
        const float* Kt = Kg + (size_t)kt*64*64;
        const float* Vt = Vg + (size_t)kt*64*64;
        // K: tf32 [kv][d]
        for (int i = tid; i < 1024; i += 128) {
            int r = i >> 4, c4 = (i & 15) << 2;
            float4 kv4 = *(const float4*)(Kt + r*64 + c4);
            uint32_t* dk = sK + r*AST + c4;
            dk[0] = f2t(kv4.x); dk[1] = f2t(kv4.y); dk[2] = f2t(kv4.z); dk[3] = f2t(kv4.w);
        }
        // V: bf16 pairs along kv: sVb[p][d] = (V[2p][d], V[2p+1][d])
        for (int i = tid; i < 512; i += 128) {
            int p = i >> 4, c4 = (i & 15) << 2;
            float4 v0 = *(const float4*)(Vt + (2*p)*64 + c4);
            float4 v1 = *(const float4*)(Vt + (2*p+1)*64 + c4);
            uint32_t* dv = sVb + p*VSTB + c4;
            dv[0] = fpack_bf16(v0.x, v1.x);
            dv[1] = fpack_bf16(v0.y, v1.y);
            dv[2] = fpack_bf16(v0.z, v1.z);
            dv[3] = fpack_bf16(v0.w, v1.w);
        }
        __syncthreads();

        // ---- S = Q K^T (tf32): warp computes 32x64 ----
        float sc[2][8][4];
        #pragma unroll
        for (int mi = 0; mi < 2; mi++)
            #pragma unroll
            for (int nt = 0; nt < 8; nt++)
                #pragma unroll
                for (int j = 0; j < 4; j++) sc[mi][nt][j] = 0.f;

        #pragma unroll
        for (int kc = 0; kc < 8; kc++) {
            int cidx = kc*8 + tg;
            uint32_t a0[2], a1[2], a2[2], a3[2];
            #pragma unroll
            for (int mi = 0; mi < 2; mi++) {
                int r = rw + 16*mi + g;
                a0[mi] = sQ[r*AST + cidx];
                a1[mi] = sQ[(r+8)*AST + cidx];
                a2[mi] = sQ[r*AST + cidx + 4];
                a3[mi] = sQ[(r+8)*AST + cidx + 4];
            }
            #pragma unroll
            for (int nt = 0; nt < 8; nt++) {
                uint32_t b0 = sK[(nt*8+g)*AST + cidx];
                uint32_t b1 = sK[(nt*8+g)*AST + cidx + 4];
                mma8(sc[0][nt], a0[0], a1[0], a2[0], a3[0], b0, b1);
                mma8(sc[1][nt], a0[1], a1[1], a2[1], a3[1], b0, b1);
            }
        }

        // ---- online softmax; P packed to bf16 in registers ----
        uint32_t pb[2][8][2];
        #pragma unroll
        for (int mi = 0; mi < 2; mi++) {
            float t0 = -1e30f, t1 = -1e30f;
            #pragma unroll
            for (int nt = 0; nt < 8; nt++) {
                t0 = fmaxf(t0, fmaxf(sc[mi][nt][0], sc[mi][nt][1]));
                t1 = fmaxf(t1, fmaxf(sc[mi][nt][2], sc[mi][nt][3]));
            }
            t0 = fmaxf(t0, __shfl_xor_sync(0xffffffffu, t0, 1));
            t0 = fmaxf(t0, __shfl_xor_sync(0xffffffffu, t0, 2));
            t1 = fmaxf(t1, __shfl_xor_sync(0xffffffffu, t1, 1));
            t1 = fmaxf(t1, __shfl_xor_sync(0xffffffffu, t1, 2));
            float mn0 = fmaxf(m[mi][0], t0), mn1 = fmaxf(m[mi][1], t1);
            float corr0 = __expf(m[mi][0] - mn0);
            float corr1 = __expf(m[mi][1] - mn1);
            m[mi][0] = mn0; m[mi][1] = mn1;

            float rs0 = 0.f, rs1 = 0.f;
            #pragma unroll
            for (int nt = 0; nt < 8; nt++) {
                float e0 = __expf(sc[mi][nt][0] - mn0);
                float e1 = __expf(sc[mi][nt][1] - mn0);
                float e2 = __expf(sc[mi][nt][2] - mn1);
                float e3 = __expf(sc[mi][nt][3] - mn1);
                rs0 += e0 + e1;
                rs1 += e2 + e3;
                pb[mi][nt][0] = fpack_bf16(e0, e1);   // row g
                pb[mi][nt][1] = fpack_bf16(e2, e3);   // row g+8
            }
            rs0 += __shfl_xor_sync(0xffffffffu, rs0, 1);
            rs0 += __shfl_xor_sync(0xffffffffu, rs0, 2);
            rs1 += __shfl_xor_sync(0xffffffffu, rs1, 1);
            rs1 += __shfl_xor_sync(0xffffffffu, rs1, 2);
            l[mi][0] = l[mi][0]*corr0 + rs0;
            l[mi][1] = l[mi][1]*corr1 + rs1;
            #pragma unroll
            for (int nt = 0; nt < 8; nt++) {
                o[mi][nt][0] *= corr0; o[mi][nt][1] *= corr0;
                o[mi][nt][2] *= corr1; o[mi][nt][3] *= corr1;
            }
        }

        // ---- O += P V (bf16, A from registers) ----
        #pragma unroll
        for (int kc = 0; kc < 4; kc++) {
            #pragma unroll
            for (int nt = 0; nt < 8; nt++) {
                uint32_t b0 = sVb[(kc*8+tg)*VSTB   + nt*8 + g];
                uint32_t b1 = sVb[(kc*8+tg+4)*VSTB + nt*8 + g];
                mma16(o[0][nt], pb[0][2*kc][0], pb[0][2*kc][1],
                               pb[0][2*kc+1][0], pb[0][2*kc+1][1], b0, b1);
                mma16(o[1][nt], pb[1][2*kc][0], pb[1][2*kc][1],
                               pb[1][2*kc+1][0], pb[1][2*kc+1][1], b0, b1);
            }
        }
    }

    // ---- epilogue: normalize, write (b, s, e) layout ----
    const int b = bh >> 4, h = bh & 15;
    #pragma unroll
    for (int mi = 0; mi < 2; mi++) {
        int s0 = qt*128 + rw + 16*mi + g;
        float inv0 = 1.0f / l[mi][0], inv1 = 1.0f / l[mi][1];
        float* out0 = g_att + ((size_t)(b*S + s0))*E + h*64;
        float* out1 = g_att + ((size_t)(b*S + s0 + 8))*E + h*64;
        #pragma unroll
        for (int nt = 0; nt < 8; nt++) {
            int cb = nt*8 + 2*tg;
            *(float2*)(out0 + cb) = make_float2(o[mi][nt][0]*inv0, o[mi][nt][1]*inv0);
            *(float2*)(out1 + cb) = make_float2(o[mi][nt][2]*inv1, o[mi][nt][3]*inv1);
        }
    }
}

// =====================================================================
// Kernel 3: output projection, split-bf16 (3-term).
// C[4096,1024] = A @ Wo^T + bo. Tile 128x128 per block, ktile 64.
// =====================================================================
#define OSTB 36
#define OPROJ_SMEM (4 * 128 * OSTB * 4)   // 73,728 B

__global__ void __launch_bounds__(256, 2) oproj_kernel(const float* __restrict__ Wo,
                                                       const float* __restrict__ bo,
                                                       float* __restrict__ out) {
    extern __shared__ uint32_t smu[];
    uint32_t* sAh = smu;                   // [128][OSTB] bf16x2 pairs
    uint32_t* sAl = sAh + 128*OSTB;
    uint32_t* sWh = sAl + 128*OSTB;
    uint32_t* sWl = sWh + 128*OSTB;

    const int tid  = threadIdx.x;
    const int w    = tid >> 5;
    const int lane = tid & 31;
    const int g    = lane >> 2;
    const int tg   = lane & 3;
    const int m0   = (w & 3) * 32;
    const int n0   = (w >> 2) * 64;
    const int mg   = blockIdx.y * 128;
    const int ng   = blockIdx.x * 128;

    float acc[2][8][4];
    #pragma unroll
    for (int mi = 0; mi < 2; mi++)
        #pragma unroll
        for (int nt = 0; nt < 8; nt++)
            #pragma unroll
            for (int j = 0; j < 4; j++) acc[mi][nt][j] = 0.f;

    for (int kt = 0; kt < E/64; kt++) {
        __syncthreads();
        for (int i = tid; i < 2048; i += 256) {
            int r = i >> 4, c4 = (i & 15) << 2;
            float4 a  = *(const float4*)(g_att + (size_t)(mg + r)*E + kt*64 + c4);
            float4 ww = *(const float4*)(Wo    + (size_t)(ng + r)*E + kt*64 + c4);
            float h0,l0,h1,l1,h2,l2,h3,l3;
            int base = r*OSTB + (c4 >> 1);
            bsplit(a.x,h0,l0); bsplit(a.y,h1,l1); bsplit(a.z,h2,l2); bsplit(a.w,h3,l3);
            sAh[base]   = fpack_bf16(h0, h1);
            sAh[base+1] = fpack_bf16(h2, h3);
            sAl[base]   = fpack_bf16(l0, l1);
            sAl[base+1] = fpack_bf16(l2, l3);
            bsplit(ww.x,h0,l0); bsplit(ww.y,h1,l1); bsplit(ww.z,h2,l2); bsplit(ww.w,h3,l3);
            sWh[base]   = fpack_bf16(h0, h1);
            sWh[base+1] = fpack_bf16(h2, h3);
            sWl[base]   = fpack_bf16(l0, l1);
            sWl[base+1] = fpack_bf16(l2, l3);
        }
        __syncthreads();

        #pragma unroll
        for (int kc = 0; kc < 4; kc++) {
            int cidx = kc*8 + tg;
            uint32_t ah[2][4], al[2][4];
            #pragma unroll
            for (int mi = 0; mi < 2; mi++) {
                int rr = m0 + 16*mi + g;
                ah[mi][0] = sAh[rr*OSTB + cidx];
                ah[mi][1] = sAh[(rr+8)*OSTB + cidx];
                ah[mi][2] = sAh[rr*OSTB + cidx + 4];
                ah[mi][3] = sAh[(rr+8)*OSTB + cidx + 4];
                al[mi][0] = sAl[rr*OSTB + cidx];
                al[mi][1] = sAl[(rr+8)*OSTB + cidx];
                al[mi][2] = sAl[rr*OSTB + cidx + 4];
                al[mi][3] = sAl[(rr+8)*OSTB + cidx + 4];
            }
            #pragma unroll
            for (int nt = 0; nt < 8; nt++) {
                int nr = n0 + nt*8 + g;
                uint32_t bh0 = sWh[nr*OSTB + cidx];
                uint32_t bh1 = sWh[nr*OSTB + cidx + 4];
                uint32_t bl0 = sWl[nr*OSTB + cidx];
                uint32_t bl1 = sWl[nr*OSTB + cidx + 4];
                #pragma unroll
                for (int mi = 0; mi < 2; mi++) {
                    mma16(acc[mi][nt], ah[mi][0], ah[mi][1], ah[mi][2], ah[mi][3], bh0, bh1);
                    mma16(acc[mi][nt], ah[mi][0], ah[mi][1], ah[mi][2], ah[mi][3], bl0, bl1);
                    mma16(acc[mi][nt], al[mi][0], al[mi][1], al[mi][2], al[mi][3], bh0, bh1);
                }
            }
        }
    }

    #pragma unroll
    for (int mi = 0; mi < 2; mi++) {
        int row = mg + m0 + 16*mi + g;
        #pragma unroll
        for (int nt = 0; nt < 8; nt++) {
            int col = ng + n0 + nt*8 + 2*tg;
            float2 bb = *(const float2*)(bo + col);
            *(float2*)(out + (size_t)row*E + col)
                = make_float2(acc[mi][nt][0] + bb.x, acc[mi][nt][1] + bb.y);
            *(float2*)(out + (size_t)(row+8)*E + col)
                = make_float2(acc[mi][nt][2] + bb.x, acc[mi][nt][3] + bb.y);
        }
    }
}

// =====================================================================
extern "C" void kernel_launch(void* const* d_in, const int* in_sizes, int n_in,
                              void* d_out, int out_size) {
    const float* x  = (const float*)d_in[0];
    const float* Wq = (const float*)d_in[1];
    const float* Wk = (const float*)d_in[2];
    const float* Wv = (const float*)d_in[3];
    const float* Wo = (const float*)d_in[4];
    const float* bo = (const float*)d_in[5];
    float* out = (float*)d_out;

    cudaFuncSetAttribute(qkv_kernel,   cudaFuncAttributeMaxDynamicSharedMemorySize, QKV_SMEM);
    cudaFuncSetAttribute(attn_kernel,  cudaFuncAttributeMaxDynamicSharedMemorySize, ATTN_SMEM);
    cudaFuncSetAttribute(oproj_kernel, cudaFuncAttributeMaxDynamicSharedMemorySize, OPROJ_SMEM);

    qkv_kernel<<<NROW / 128, 256, QKV_SMEM>>>(x, Wq, Wk, Wv);
    attn_kernel<<<dim3(S/128, BH), 128, ATTN_SMEM>>>();
    oproj_kernel<<<dim3(E/128, (B*S)/128), 256, OPROJ_SMEM>>>(Wo, bo, out);
}

// round 6
// speedup vs baseline: 3.5928x; 1.0006x over previous
#include <cuda_runtime.h>
#include <cuda_bf16.h>
#include <cstdint>

#define B 2
#define S 2048
#define E 1024
#define H 16
#define D 64
#define BH (B*H)            // 32
#define NROW (B*S*H)        // 65536

// Scratch (allocation-free rule: __device__ globals)
__device__ float g_q[B*H*S*D];
__device__ float g_k[B*H*S*D];
__device__ float g_v[B*H*S*D];
__device__ float g_att[B*S*E];

// ---------------------------------------------------------------------
// helpers
// ---------------------------------------------------------------------
__device__ __forceinline__ uint32_t f2t(float f) {
    uint32_t u;
    asm("cvt.rna.tf32.f32 %0, %1;" : "=r"(u) : "f"(f));
    return u;
}

__device__ __forceinline__ uint32_t fpack_bf16(float lo, float hi) {
    __nv_bfloat162 h = __floats2bfloat162_rn(lo, hi);   // .x = lo (low 16 bits)
    return *(uint32_t*)&h;
}

// tf32 m16n8k8
__device__ __forceinline__ void mma8(float* c, uint32_t a0, uint32_t a1,
                                     uint32_t a2, uint32_t a3,
                                     uint32_t b0, uint32_t b1) {
    asm volatile(
        "mma.sync.aligned.m16n8k8.row.col.f32.tf32.tf32.f32 "
        "{%0,%1,%2,%3},{%4,%5,%6,%7},{%8,%9},{%0,%1,%2,%3};"
        : "+f"(c[0]), "+f"(c[1]), "+f"(c[2]), "+f"(c[3])
        : "r"(a0), "r"(a1), "r"(a2), "r"(a3), "r"(b0), "r"(b1));
}

// bf16 m16n8k16
__device__ __forceinline__ void mma16(float* c, uint32_t a0, uint32_t a1,
                                      uint32_t a2, uint32_t a3,
                                      uint32_t b0, uint32_t b1) {
    asm volatile(
        "mma.sync.aligned.m16n8k16.row.col.f32.bf16.bf16.f32 "
        "{%0,%1,%2,%3},{%4,%5,%6,%7},{%8,%9},{%0,%1,%2,%3};"
        : "+f"(c[0]), "+f"(c[1]), "+f"(c[2]), "+f"(c[3])
        : "r"(a0), "r"(a1), "r"(a2), "r"(a3), "r"(b0), "r"(b1));
}

// split a float into bf16 hi/lo
__device__ __forceinline__ void bsplit(float f, float& hi, float& lo) {
    __nv_bfloat16 h = __float2bfloat16_rn(f);
    hi = __bfloat162float(h);
    lo = f - hi;
}

// =====================================================================
// Kernel 1: QKV projection, split-bf16 (3-term) MMA.
// 512 threads (16 warps); block = 128 x-rows; N = 192 (q|k|v).
// warp layout: (w & 7) -> 16-row group, (w >> 3) -> 96-col group.
// 48 acc regs/thread -> ~33% occupancy (vs 12% at R4).
// =====================================================================
#define QSTB 36
#define QKV_SMEM ((128*QSTB*2 + 192*QSTB*2) * 4)   // 92,160 B

__global__ void __launch_bounds__(512, 1) qkv_kernel(const float* __restrict__ x,
                                                     const float* __restrict__ Wq,
                                                     const float* __restrict__ Wk,
                                                     const float* __restrict__ Wv) {
    extern __shared__ uint32_t smu[];
    uint32_t* sXh = smu;                  // [128][QSTB]
    uint32_t* sXl = sXh + 128*QSTB;
    uint32_t* sWh = sXl + 128*QSTB;       // [192][QSTB]
    uint32_t* sWl = sWh + 192*QSTB;

    const int tid  = threadIdx.x;
    const int w    = tid >> 5;
    const int lane = tid & 31;
    const int g    = lane >> 2;
    const int tg   = lane & 3;
    const int wr   = w & 7;               // row group
    const int wc   = w >> 3;              // col group (0,1)
    const int g0   = blockIdx.x * 128;

    // Stage weights hi/lo (packed pairs)
    for (int i = tid; i < 3072; i += 512) {
        int m = i >> 10, r = (i >> 4) & 63, c4 = (i & 15) << 2;
        const float* Ws = (m == 0) ? Wq : (m == 1) ? Wk : Wv;
        float4 v = *(const float4*)(Ws + r*64 + c4);
        float h0,l0,h1,l1,h2,l2,h3,l3;
        bsplit(v.x,h0,l0); bsplit(v.y,h1,l1); bsplit(v.z,h2,l2); bsplit(v.w,h3,l3);
        int base = (m*64 + r)*QSTB + (c4 >> 1);
        sWh[base]   = fpack_bf16(h0, h1);
        sWh[base+1] = fpack_bf16(h2, h3);
        sWl[base]   = fpack_bf16(l0, l1);
        sWl[base+1] = fpack_bf16(l2, l3);
    }
    // Stage x hi/lo
    for (int i = tid; i < 2048; i += 512) {
        int r = i >> 4, c4 = (i & 15) << 2;
        float4 v = *(const float4*)(x + (size_t)(g0 + r)*64 + c4);
        float h0,l0,h1,l1,h2,l2,h3,l3;
        bsplit(v.x,h0,l0); bsplit(v.y,h1,l1); bsplit(v.z,h2,l2); bsplit(v.w,h3,l3);
        int base = r*QSTB + (c4 >> 1);
        sXh[base]   = fpack_bf16(h0, h1);
        sXh[base+1] = fpack_bf16(h2, h3);
        sXl[base]   = fpack_bf16(l0, l1);
        sXl[base+1] = fpack_bf16(l2, l3);
    }
    __syncthreads();

    float acc[12][4];
    #pragma unroll
    for (int nt = 0; nt < 12; nt++)
        #pragma unroll
        for (int j = 0; j < 4; j++) acc[nt][j] = 0.f;

    const int r0 = 16*wr + g;
    #pragma unroll
    for (int kc = 0; kc < 4; kc++) {           // 4 chunks of k16
        int cidx = kc*8 + tg;
        uint32_t ah0 = sXh[r0*QSTB + cidx],     ah1 = sXh[(r0+8)*QSTB + cidx];
        uint32_t ah2 = sXh[r0*QSTB + cidx + 4], ah3 = sXh[(r0+8)*QSTB + cidx + 4];
        uint32_t al0 = sXl[r0*QSTB + cidx],     al1 = sXl[(r0+8)*QSTB + cidx];
        uint32_t al2 = sXl[r0*QSTB + cidx + 4], al3 = sXl[(r0+8)*QSTB + cidx + 4];
        #pragma unroll
        for (int nt = 0; nt < 12; nt++) {
            int nr = (wc*12 + nt)*8 + g;
            uint32_t bh0 = sWh[nr*QSTB + cidx], bh1 = sWh[nr*QSTB + cidx + 4];
            uint32_t bl0 = sWl[nr*QSTB + cidx], bl1 = sWl[nr*QSTB + cidx + 4];
            mma16(acc[nt], ah0, ah1, ah2, ah3, bh0, bh1);
            mma16(acc[nt], ah0, ah1, ah2, ah3, bl0, bl1);
            mma16(acc[nt], al0, al1, al2, al3, bh0, bh1);
        }
    }

    // Store: row gr -> (b,s,h); out layout (b,h,s,d)
    int gr0 = g0 + r0, gr1 = gr0 + 8;
    int b0 = gr0 >> 15, s0 = (gr0 & 32767) >> 4, h0 = gr0 & 15;
    int b1 = gr1 >> 15, s1 = (gr1 & 32767) >> 4, h1 = gr1 & 15;
    size_t orow0 = ((size_t)(b0*H + h0)*S + s0) * 64;
    size_t orow1 = ((size_t)(b1*H + h1)*S + s1) * 64;
    #pragma unroll
    for (int nt = 0; nt < 12; nt++) {
        int gn  = wc*12 + nt;              // global n-tile 0..23
        int mat = gn >> 3;
        int e   = (gn & 7)*8 + 2*tg;
        float* dst = (mat == 0) ? g_q : (mat == 1) ? g_k : g_v;
        *(float2*)(dst + orow0 + e) = make_float2(acc[nt][0], acc[nt][1]);
        *(float2*)(dst + orow1 + e) = make_float2(acc[nt][2], acc[nt][3]);
    }
}

// =====================================================================
// Kernel 2: flash attention. QK^T in tf32 (m16n8k8), PV in bf16
// (m16n8k16) with A-fragments straight from registers (no sP).
// Br=128, Bc=64, 4 warps; warp owns 32 q-rows. Q pre-scaled by
// 0.125*log2(e) -> base-2 softmax (exp2f, MUFU.EX2 direct).
// 3 CTAs/SM for phase overlap (MMA of one CTA hides MUFU of another).
// =====================================================================
#define AST 68
#define VSTB 72
#define ATTN_SMEM ((128*AST + 64*AST + 32*VSTB) * 4)   // 61,440 B

__global__ void __launch_bounds__(128, 3) attn_kernel() {
    extern __shared__ uint32_t smu[];
    uint32_t* sQ  = smu;               // [128][AST]  tf32 (pre-scaled)
    uint32_t* sK  = sQ + 128*AST;      // [64][AST]   tf32 [kv][d]
    uint32_t* sVb = sK + 64*AST;       // [32][VSTB]  bf16x2 pairs [kv/2][d]

    const int tid  = threadIdx.x;
    const int w    = tid >> 5;
    const int lane = tid & 31;
    const int g    = lane >> 2;
    const int tg   = lane & 3;
    const int qt   = blockIdx.x;
    const int bh   = blockIdx.y;

    const float* Qg = g_q + (size_t)bh*S*D + (size_t)qt*128*D;
    const float* Kg = g_k + (size_t)bh*S*D;
    const float* Vg = g_v + (size_t)bh*S*D;

    // Load + convert Q tile (128x64), pre-scaled by 0.125*log2(e)
    const float QSC = 0.125f * 1.4426950408889634f;
    for (int i = tid; i < 2048; i += 128) {
        int r = i >> 4, c4 = (i & 15) << 2;
        float4 v = *(const float4*)(Qg + r*64 + c4);
        uint32_t* dst = sQ + r*AST + c4;
        dst[0] = f2t(v.x*QSC); dst[1] = f2t(v.y*QSC);
        dst[2] = f2t(v.z*QSC); dst[3] = f2t(v.w*QSC);
    }

    const int rw = 32*w;
    float m[2][2], l[2][2];
    float o[2][8][4];
    #pragma unroll
    for (int mi = 0; mi < 2; mi++) {
        m[mi][0] = m[mi][1] = -1e30f;
        l[mi][0] = l[mi][1] = 0.f;
        #pragma unroll
        for (int nt = 0; nt < 8; nt++)
            #pragma unroll
            for (int j = 0; j < 4; j++) o[mi][nt][j] = 0.f;
    }

    for (int kt = 0; kt < S/64; kt++) {
        __syncthreads();
        const float* Kt = Kg + (size_t)kt*64*64;
        const float* Vt = Vg + (size_t)kt*64*64;
        // K: tf32 [kv][d]
        for (int i = tid; i < 1024; i += 128) {
            int r = i >> 4, c4 = (i & 15) << 2;
            float4 kv4 = *(const float4*)(Kt + r*64 + c4);
            uint32_t* dk = sK + r*AST + c4;
            dk[0] = f2t(kv4.x); dk[1] = f2t(kv4.y); dk[2] = f2t(kv4.z); dk[3] = f2t(kv4.w);
        }
        // V: bf16 pairs along kv: sVb[p][d] = (V[2p][d], V[2p+1][d])
        for (int i = tid; i < 512; i += 128) {
            int p = i >> 4, c4 = (i & 15) << 2;
            float4 v0 = *(const float4*)(Vt + (2*p)*64 + c4);
            float4 v1 = *(const float4*)(Vt + (2*p+1)*64 + c4);
            uint32_t* dv = sVb + p*VSTB + c4;
            dv[0] = fpack_bf16(v0.x, v1.x);
            dv[1] = fpack_bf16(v0.y, v1.y);
            dv[2] = fpack_bf16(v0.z, v1.z);
            dv[3] = fpack_bf16(v0.w, v1.w);
        }
        __syncthreads();

        // ---- S = Q K^T (tf32): warp computes 32x64 ----
        float sc[2][8][4];
        #pragma unroll
        for (int mi = 0; mi < 2; mi++)
            #pragma unroll
            for (int nt = 0; nt < 8; nt++)
                #pragma unroll
                for (int j = 0; j < 4; j++) sc[mi][nt][j] = 0.f;

        #pragma unroll
        for (int kc = 0; kc < 8; kc++) {
            int cidx = kc*8 + tg;
            uint32_t a0[2], a1[2], a2[2], a3[2];
            #pragma unroll
            for (int mi = 0; mi < 2; mi++) {
                int r = rw + 16*mi + g;
                a0[mi] = sQ[r*AST + cidx];
                a1[mi] = sQ[(r+8)*AST + cidx];
                a2[mi] = sQ[r*AST + cidx + 4];
                a3[mi] = sQ[(r+8)*AST + cidx + 4];
            }
            #pragma unroll
            for (int nt = 0; nt < 8; nt++) {
                uint32_t b0 = sK[(nt*8+g)*AST + cidx];
                uint32_t b1 = sK[(nt*8+g)*AST + cidx + 4];
                mma8(sc[0][nt], a0[0], a1[0], a2[0], a3[0], b0, b1);
                mma8(sc[1][nt], a0[1], a1[1], a2[1], a3[1], b0, b1);
            }
        }

        // ---- online softmax (base-2); P packed to bf16 in registers ----
        uint32_t pb[2][8][2];
        #pragma unroll
        for (int mi = 0; mi < 2; mi++) {
            float t0 = -1e30f, t1 = -1e30f;
            #pragma unroll
            for (int nt = 0; nt < 8; nt++) {
                t0 = fmaxf(t0, fmaxf(sc[mi][nt][0], sc[mi][nt][1]));
                t1 = fmaxf(t1, fmaxf(sc[mi][nt][2], sc[mi][nt][3]));
            }
            t0 = fmaxf(t0, __shfl_xor_sync(0xffffffffu, t0, 1));
            t0 = fmaxf(t0, __shfl_xor_sync(0xffffffffu, t0, 2));
            t1 = fmaxf(t1, __shfl_xor_sync(0xffffffffu, t1, 1));
            t1 = fmaxf(t1, __shfl_xor_sync(0xffffffffu, t1, 2));
            float mn0 = fmaxf(m[mi][0], t0), mn1 = fmaxf(m[mi][1], t1);
            float corr0 = exp2f(m[mi][0] - mn0);
            float corr1 = exp2f(m[mi][1] - mn1);
            m[mi][0] = mn0; m[mi][1] = mn1;

            float rs0 = 0.f, rs1 = 0.f;
            #pragma unroll
            for (int nt = 0; nt < 8; nt++) {
                float e0 = exp2f(sc[mi][nt][0] - mn0);
                float e1 = exp2f(sc[mi][nt][1] - mn0);
                float e2 = exp2f(sc[mi][nt][2] - mn1);
                float e3 = exp2f(sc[mi][nt][3] - mn1);
                rs0 += e0 + e1;
                rs1 += e2 + e3;
                pb[mi][nt][0] = fpack_bf16(e0, e1);   // row g
                pb[mi][nt][1] = fpack_bf16(e2, e3);   // row g+8
            }
            rs0 += __shfl_xor_sync(0xffffffffu, rs0, 1);
            rs0 += __shfl_xor_sync(0xffffffffu, rs0, 2);
            rs1 += __shfl_xor_sync(0xffffffffu, rs1, 1);
            rs1 += __shfl_xor_sync(0xffffffffu, rs1, 2);
            l[mi][0] = l[mi][0]*corr0 + rs0;
            l[mi][1] = l[mi][1]*corr1 + rs1;
            #pragma unroll
            for (int nt = 0; nt < 8; nt++) {
                o[mi][nt][0] *= corr0; o[mi][nt][1] *= corr0;
                o[mi][nt][2] *= corr1; o[mi][nt][3] *= corr1;
            }
        }

        // ---- O += P V (bf16, A from registers) ----
        #pragma unroll
        for (int kc = 0; kc < 4; kc++) {
            #pragma unroll
            for (int nt = 0; nt < 8; nt++) {
                uint32_t b0 = sVb[(kc*8+tg)*VSTB   + nt*8 + g];
                uint32_t b1 = sVb[(kc*8+tg+4)*VSTB + nt*8 + g];
                mma16(o[0][nt], pb[0][2*kc][0], pb[0][2*kc][1],
                               pb[0][2*kc+1][0], pb[0][2*kc+1][1], b0, b1);
                mma16(o[1][nt], pb[1][2*kc][0], pb[1][2*kc][1],
                               pb[1][2*kc+1][0], pb[1][2*kc+1][1], b0, b1);
            }
        }
    }

    // ---- epilogue: normalize, write (b, s, e) layout ----
    const int b = bh >> 4, h = bh & 15;
    #pragma unroll
    for (int mi = 0; mi < 2; mi++) {
        int s0 = qt*128 + rw + 16*mi + g;
        float inv0 = 1.0f / l[mi][0], inv1 = 1.0f / l[mi][1];
        float* out0 = g_att + ((size_t)(b*S + s0))*E + h*64;
        float* out1 = g_att + ((size_t)(b*S + s0 + 8))*E + h*64;
        #pragma unroll
        for (int nt = 0; nt < 8; nt++) {
            int cb = nt*8 + 2*tg;
            *(float2*)(out0 + cb) = make_float2(o[mi][nt][0]*inv0, o[mi][nt][1]*inv0);
            *(float2*)(out1 + cb) = make_float2(o[mi][nt][2]*inv1, o[mi][nt][3]*inv1);
        }
    }
}

// =====================================================================
// Kernel 3: output projection, split-bf16 (3-term).
// C[4096,1024] = A @ Wo^T + bo. Tile 128x128 per block, ktile 64.
// =====================================================================
#define OSTB 36
#define OPROJ_SMEM (4 * 128 * OSTB * 4)   // 73,728 B

__global__ void __launch_bounds__(256, 2) oproj_kernel(const float* __restrict__ Wo,
                                                       const float* __restrict__ bo,
                                                       float* __restrict__ out) {
    extern __shared__ uint32_t smu[];
    uint32_t* sAh = smu;                   // [128][OSTB] bf16x2 pairs
    uint32_t* sAl = sAh + 128*OSTB;
    uint32_t* sWh = sAl + 128*OSTB;
    uint32_t* sWl = sWh + 128*OSTB;

    const int tid  = threadIdx.x;
    const int w    = tid >> 5;
    const int lane = tid & 31;
    const int g    = lane >> 2;
    const int tg   = lane & 3;
    const int m0   = (w & 3) * 32;
    const int n0   = (w >> 2) * 64;
    const int mg   = blockIdx.y * 128;
    const int ng   = blockIdx.x * 128;

    float acc[2][8][4];
    #pragma unroll
    for (int mi = 0; mi < 2; mi++)
        #pragma unroll
        for (int nt = 0; nt < 8; nt++)
            #pragma unroll
            for (int j = 0; j < 4; j++) acc[mi][nt][j] = 0.f;

    for (int kt = 0; kt < E/64; kt++) {
        __syncthreads();
        for (int i = tid; i < 2048; i += 256) {
            int r = i >> 4, c4 = (i & 15) << 2;
            float4 a  = *(const float4*)(g_att + (size_t)(mg + r)*E + kt*64 + c4);
            float4 ww = *(const float4*)(Wo    + (size_t)(ng + r)*E + kt*64 + c4);
            float h0,l0,h1,l1,h2,l2,h3,l3;
            int base = r*OSTB + (c4 >> 1);
            bsplit(a.x,h0,l0); bsplit(a.y,h1,l1); bsplit(a.z,h2,l2); bsplit(a.w,h3,l3);
            sAh[base]   = fpack_bf16(h0, h1);
            sAh[base+1] = fpack_bf16(h2, h3);
            sAl[base]   = fpack_bf16(l0, l1);
            sAl[base+1] = fpack_bf16(l2, l3);
            bsplit(ww.x,h0,l0); bsplit(ww.y,h1,l1); bsplit(ww.z,h2,l2); bsplit(ww.w,h3,l3);
            sWh[base]   = fpack_bf16(h0, h1);
            sWh[base+1] = fpack_bf16(h2, h3);
            sWl[base]   = fpack_bf16(l0, l1);
            sWl[base+1] = fpack_bf16(l2, l3);
        }
        __syncthreads();

        #pragma unroll
        for (int kc = 0; kc < 4; kc++) {
            int cidx = kc*8 + tg;
            uint32_t ah[2][4], al[2][4];
            #pragma unroll
            for (int mi = 0; mi < 2; mi++) {
                int rr = m0 + 16*mi + g;
                ah[mi][0] = sAh[rr*OSTB + cidx];
                ah[mi][1] = sAh[(rr+8)*OSTB + cidx];
                ah[mi][2] = sAh[rr*OSTB + cidx + 4];
                ah[mi][3] = sAh[(rr+8)*OSTB + cidx + 4];
                al[mi][0] = sAl[rr*OSTB + cidx];
                al[mi][1] = sAl[(rr+8)*OSTB + cidx];
                al[mi][2] = sAl[rr*OSTB + cidx + 4];
                al[mi][3] = sAl[(rr+8)*OSTB + cidx + 4];
            }
            #pragma unroll
            for (int nt = 0; nt < 8; nt++) {
                int nr = n0 + nt*8 + g;
                uint32_t bh0 = sWh[nr*OSTB + cidx];
                uint32_t bh1 = sWh[nr*OSTB + cidx + 4];
                uint32_t bl0 = sWl[nr*OSTB + cidx];
                uint32_t bl1 = sWl[nr*OSTB + cidx + 4];
                #pragma unroll
                for (int mi = 0; mi < 2; mi++) {
                    mma16(acc[mi][nt], ah[mi][0], ah[mi][1], ah[mi][2], ah[mi][3], bh0, bh1);
                    mma16(acc[mi][nt], ah[mi][0], ah[mi][1], ah[mi][2], ah[mi][3], bl0, bl1);
                    mma16(acc[mi][nt], al[mi][0], al[mi][1], al[mi][2], al[mi][3], bh0, bh1);
                }
            }
        }
    }

    #pragma unroll
    for (int mi = 0; mi < 2; mi++) {
        int row = mg + m0 + 16*mi + g;
        #pragma unroll
        for (int nt = 0; nt < 8; nt++) {
            int col = ng + n0 + nt*8 + 2*tg;
            float2 bb = *(const float2*)(bo + col);
            *(float2*)(out + (size_t)row*E + col)
                = make_float2(acc[mi][nt][0] + bb.x, acc[mi][nt][1] + bb.y);
            *(float2*)(out + (size_t)(row+8)*E + col)
                = make_float2(acc[mi][nt][2] + bb.x, acc[mi][nt][3] + bb.y);
        }
    }
}

// =====================================================================
extern "C" void kernel_launch(void* const* d_in, const int* in_sizes, int n_in,
                              void* d_out, int out_size) {
    const float* x  = (const float*)d_in[0];
    const float* Wq = (const float*)d_in[1];
    const float* Wk = (const float*)d_in[2];
    const float* Wv = (const float*)d_in[3];
    const float* Wo = (const float*)d_in[4];
    const float* bo = (const float*)d_in[5];
    float* out = (float*)d_out;

    cudaFuncSetAttribute(qkv_kernel,   cudaFuncAttributeMaxDynamicSharedMemorySize, QKV_SMEM);
    cudaFuncSetAttribute(attn_kernel,  cudaFuncAttributeMaxDynamicSharedMemorySize, ATTN_SMEM);
    cudaFuncSetAttribute(oproj_kernel, cudaFuncAttributeMaxDynamicSharedMemorySize, OPROJ_SMEM);

    qkv_kernel<<<NROW / 128, 512, QKV_SMEM>>>(x, Wq, Wk, Wv);
    attn_kernel<<<dim3(S/128, BH), 128, ATTN_SMEM>>>();
    oproj_kernel<<<dim3(E/128, (B*S)/128), 256, OPROJ_SMEM>>>(Wo, bo, out);
}

// round 7
// speedup vs baseline: 4.1641x; 1.1590x over previous
#include <cuda_runtime.h>
#include <cuda_bf16.h>
#include <cstdint>

#define B 2
#define S 2048
#define E 1024
#define H 16
#define D 64
#define BH (B*H)            // 32
#define NROW (B*S*H)        // 65536

// Scratch (allocation-free rule: __device__ globals)
__device__ uint32_t g_q[BH*S*D];        // tf32 bits of q * 0.125*log2(e)
__device__ uint32_t g_k[BH*S*D];        // tf32 bits of k
__device__ uint32_t g_vb[BH*(S/2)*D];   // bf16x2: (V[2p][d], V[2p+1][d])
__device__ uint32_t g_ah[B*S*(E/2)];    // attn out, bf16 hi, packed pairs along e
__device__ uint32_t g_al[B*S*(E/2)];    // attn out, bf16 lo
__device__ uint32_t g_wh[E*(E/2)];      // Wo hi, packed pairs along k
__device__ uint32_t g_wl[E*(E/2)];      // Wo lo

// ---------------------------------------------------------------------
// helpers
// ---------------------------------------------------------------------
__device__ __forceinline__ uint32_t f2t(float f) {
    uint32_t u;
    asm("cvt.rna.tf32.f32 %0, %1;" : "=r"(u) : "f"(f));
    return u;
}
__device__ __forceinline__ uint32_t fpack_bf16(float lo, float hi) {
    __nv_bfloat162 h = __floats2bfloat162_rn(lo, hi);   // .x = lo (low 16 bits)
    return *(uint32_t*)&h;
}
__device__ __forceinline__ void bsplit(float f, float& hi, float& lo) {
    __nv_bfloat16 h = __float2bfloat16_rn(f);
    hi = __bfloat162float(h);
    lo = f - hi;
}
__device__ __forceinline__ uint32_t saddr(const void* p) {
    return (uint32_t)__cvta_generic_to_shared(p);
}
__device__ __forceinline__ void cp16(uint32_t dst, const void* src) {
    asm volatile("cp.async.cg.shared.global [%0], [%1], 16;" :: "r"(dst), "l"(src));
}
#define CP_COMMIT() asm volatile("cp.async.commit_group;")
#define CP_WAIT0()  asm volatile("cp.async.wait_group 0;")

// tf32 m16n8k8
__device__ __forceinline__ void mma8(float* c, uint32_t a0, uint32_t a1,
                                     uint32_t a2, uint32_t a3,
                                     uint32_t b0, uint32_t b1) {
    asm volatile(
        "mma.sync.aligned.m16n8k8.row.col.f32.tf32.tf32.f32 "
        "{%0,%1,%2,%3},{%4,%5,%6,%7},{%8,%9},{%0,%1,%2,%3};"
        : "+f"(c[0]), "+f"(c[1]), "+f"(c[2]), "+f"(c[3])
        : "r"(a0), "r"(a1), "r"(a2), "r"(a3), "r"(b0), "r"(b1));
}
// bf16 m16n8k16
__device__ __forceinline__ void mma16(float* c, uint32_t a0, uint32_t a1,
                                      uint32_t a2, uint32_t a3,
                                      uint32_t b0, uint32_t b1) {
    asm volatile(
        "mma.sync.aligned.m16n8k16.row.col.f32.bf16.bf16.f32 "
        "{%0,%1,%2,%3},{%4,%5,%6,%7},{%8,%9},{%0,%1,%2,%3};"
        : "+f"(c[0]), "+f"(c[1]), "+f"(c[2]), "+f"(c[3])
        : "r"(a0), "r"(a1), "r"(a2), "r"(a3), "r"(b0), "r"(b1));
}

// =====================================================================
// Kernel 0: one-shot Wo split into packed bf16 hi/lo (pairs along k).
// =====================================================================
__global__ void __launch_bounds__(256) wsplit_kernel(const float* __restrict__ Wo) {
    int i = blockIdx.x * 256 + threadIdx.x;        // word index 0..E*E/2-1
    float2 v = *(const float2*)(Wo + 2*(size_t)i);
    float h0,l0,h1,l1;
    bsplit(v.x,h0,l0); bsplit(v.y,h1,l1);
    g_wh[i] = fpack_bf16(h0, h1);
    g_wl[i] = fpack_bf16(l0, l1);
}

// =====================================================================
// Kernel 1: QKV projection, split-bf16 (3-term) MMA.
// 512 threads (16 warps); block = 128 x-rows (8 s x 16 h); N=192.
// Outputs: q/k as tf32 words (q pre-scaled), v as s-paired bf16x2 words.
// =====================================================================
#define QSTB 36
#define QKV_SMEM ((128*QSTB*2 + 192*QSTB*2) * 4 + 128*66*2)   // 109,056 B

__global__ void __launch_bounds__(512, 1) qkv_kernel(const float* __restrict__ x,
                                                     const float* __restrict__ Wq,
                                                     const float* __restrict__ Wk,
                                                     const float* __restrict__ Wv) {
    extern __shared__ uint32_t smu[];
    uint32_t* sXh = smu;                  // [128][QSTB]
    uint32_t* sXl = sXh + 128*QSTB;
    uint32_t* sWh = sXl + 128*QSTB;       // [192][QSTB]
    uint32_t* sWl = sWh + 192*QSTB;
    uint16_t* sVs = (uint16_t*)(sWl + 192*QSTB);   // [128][66] bf16 v staging

    const int tid  = threadIdx.x;
    const int w    = tid >> 5;
    const int lane = tid & 31;
    const int g    = lane >> 2;
    const int tg   = lane & 3;
    const int wr   = w & 7;               // row group
    const int wc   = w >> 3;              // col group (0,1)
    const int g0   = blockIdx.x * 128;
    const float QSC = 0.125f * 1.4426950408889634f;

    // Stage weights hi/lo (packed pairs)
    for (int i = tid; i < 3072; i += 512) {
        int m = i >> 10, r = (i >> 4) & 63, c4 = (i & 15) << 2;
        const float* Ws = (m == 0) ? Wq : (m == 1) ? Wk : Wv;
        float4 v = *(const float4*)(Ws + r*64 + c4);
        float h0,l0,h1,l1,h2,l2,h3,l3;
        bsplit(v.x,h0,l0); bsplit(v.y,h1,l1); bsplit(v.z,h2,l2); bsplit(v.w,h3,l3);
        int base = (m*64 + r)*QSTB + (c4 >> 1);
        sWh[base]   = fpack_bf16(h0, h1);
        sWh[base+1] = fpack_bf16(h2, h3);
        sWl[base]   = fpack_bf16(l0, l1);
        sWl[base+1] = fpack_bf16(l2, l3);
    }
    // Stage x hi/lo
    for (int i = tid; i < 2048; i += 512) {
        int r = i >> 4, c4 = (i & 15) << 2;
        float4 v = *(const float4*)(x + (size_t)(g0 + r)*64 + c4);
        float h0,l0,h1,l1,h2,l2,h3,l3;
        bsplit(v.x,h0,l0); bsplit(v.y,h1,l1); bsplit(v.z,h2,l2); bsplit(v.w,h3,l3);
        int base = r*QSTB + (c4 >> 1);
        sXh[base]   = fpack_bf16(h0, h1);
        sXh[base+1] = fpack_bf16(h2, h3);
        sXl[base]   = fpack_bf16(l0, l1);
        sXl[base+1] = fpack_bf16(l2, l3);
    }
    __syncthreads();

    float acc[12][4];
    #pragma unroll
    for (int nt = 0; nt < 12; nt++)
        #pragma unroll
        for (int j = 0; j < 4; j++) acc[nt][j] = 0.f;

    const int r0 = 16*wr + g;
    #pragma unroll
    for (int kc = 0; kc < 4; kc++) {
        int cidx = kc*8 + tg;
        uint32_t ah0 = sXh[r0*QSTB + cidx],     ah1 = sXh[(r0+8)*QSTB + cidx];
        uint32_t ah2 = sXh[r0*QSTB + cidx + 4], ah3 = sXh[(r0+8)*QSTB + cidx + 4];
        uint32_t al0 = sXl[r0*QSTB + cidx],     al1 = sXl[(r0+8)*QSTB + cidx];
        uint32_t al2 = sXl[r0*QSTB + cidx + 4], al3 = sXl[(r0+8)*QSTB + cidx + 4];
        #pragma unroll
        for (int nt = 0; nt < 12; nt++) {
            int nr = (wc*12 + nt)*8 + g;
            uint32_t bh0 = sWh[nr*QSTB + cidx], bh1 = sWh[nr*QSTB + cidx + 4];
            uint32_t bl0 = sWl[nr*QSTB + cidx], bl1 = sWl[nr*QSTB + cidx + 4];
            mma16(acc[nt], ah0, ah1, ah2, ah3, bh0, bh1);
            mma16(acc[nt], ah0, ah1, ah2, ah3, bl0, bl1);
            mma16(acc[nt], al0, al1, al2, al3, bh0, bh1);
        }
    }

    // Store q/k (tf32 words, (b,h,s,d) layout); stage v in smem bf16
    int gr0 = g0 + r0, gr1 = gr0 + 8;
    int b0 = gr0 >> 15, s0 = (gr0 & 32767) >> 4, h0 = gr0 & 15;
    int b1 = gr1 >> 15, s1 = (gr1 & 32767) >> 4, h1 = gr1 & 15;
    size_t orow0 = ((size_t)(b0*H + h0)*S + s0) * 64;
    size_t orow1 = ((size_t)(b1*H + h1)*S + s1) * 64;
    #pragma unroll
    for (int nt = 0; nt < 12; nt++) {
        int gn = wc*12 + nt;
        int e  = (gn & 7)*8 + 2*tg;
        if (gn < 16) {
            uint32_t* dst = (gn < 8) ? g_q : g_k;
            float sc_ = (gn < 8) ? QSC : 1.0f;
            *(uint2*)(dst + orow0 + e) = make_uint2(f2t(acc[nt][0]*sc_), f2t(acc[nt][1]*sc_));
            *(uint2*)(dst + orow1 + e) = make_uint2(f2t(acc[nt][2]*sc_), f2t(acc[nt][3]*sc_));
        } else {
            *(uint32_t*)(sVs + r0*66 + e)      = fpack_bf16(acc[nt][0], acc[nt][1]);
            *(uint32_t*)(sVs + (r0+8)*66 + e)  = fpack_bf16(acc[nt][2], acc[nt][3]);
        }
    }
    __syncthreads();

    // Pack V into s-pairs: word = (V[s_even], V[s_odd]) at fixed (b,h,d)
    // block rows: s_in_block = row>>4 (0..7), h = row&15
    {
        int b_idx = g0 >> 15;
        int sb    = (g0 & 32767) >> 4;      // s base of this block (multiple of 8)
        for (int wi = tid; wi < 4096; wi += 512) {
            int pr = wi >> 6, e = wi & 63;
            int t = pr >> 4, h = pr & 15;
            int rowA = 32*t + h;            // s_in_block = 2t
            int rowB = rowA + 16;           // s_in_block = 2t+1
            uint32_t a  = sVs[rowA*66 + e];
            uint32_t bq = sVs[rowB*66 + e];
            uint32_t word = (a & 0xffffu) | (bq << 16);
            int bh_ = b_idx*16 + h;
            g_vb[((size_t)bh_*(S/2) + (sb>>1) + t)*64 + e] = word;
        }
    }
}

// =====================================================================
// Kernel 2: flash attention. Pure cp.async staging (no conversions),
// double-buffered K/V. QK^T tf32, PV bf16 from registers. Br=128, Bc=64.
// =====================================================================
#define AST 68
#define VSTB 72
#define ATTN_SMEM ((128*AST + 2*64*AST + 2*32*VSTB) * 4)   // 88,064 B
#define NT_ATT (S/64)

__global__ void __launch_bounds__(128, 2) attn_kernel() {
    extern __shared__ uint32_t smu[];
    uint32_t* sQ = smu;                                   // [128][AST]
    uint32_t* sKb[2] = { smu + 128*AST, smu + 128*AST + 64*AST };
    uint32_t* sVv[2] = { smu + 128*AST + 2*64*AST,
                         smu + 128*AST + 2*64*AST + 32*VSTB };

    const int tid  = threadIdx.x;
    const int w    = tid >> 5;
    const int lane = tid & 31;
    const int g    = lane >> 2;
    const int tg   = lane & 3;
    const int qt   = blockIdx.x;
    const int bh   = blockIdx.y;

    const uint32_t* Qg = g_q  + (size_t)bh*S*D + (size_t)qt*128*D;
    const uint32_t* Kg = g_k  + (size_t)bh*S*D;
    const uint32_t* Vg = g_vb + (size_t)bh*(S/2)*D;

    // prologue: Q + tile 0 (one async group)
    for (int i = tid; i < 2048; i += 128) {
        int r = i >> 4, sg = i & 15;
        cp16(saddr(sQ + r*AST + sg*4), Qg + r*64 + sg*4);
    }
    {
        const uint32_t* Kt = Kg;
        const uint32_t* Vt = Vg;
        for (int i = tid; i < 1024; i += 128) {
            int r = i >> 4, sg = i & 15;
            cp16(saddr(sKb[0] + r*AST + sg*4), Kt + r*64 + sg*4);
        }
        for (int i = tid; i < 512; i += 128) {
            int r = i >> 4, sg = i & 15;
            cp16(saddr(sVv[0] + r*VSTB + sg*4), Vt + r*64 + sg*4);
        }
        CP_COMMIT();
    }

    const int rw = 32*w;
    float m[2][2], l[2][2];
    float o[2][8][4];
    #pragma unroll
    for (int mi = 0; mi < 2; mi++) {
        m[mi][0] = m[mi][1] = -1e30f;
        l[mi][0] = l[mi][1] = 0.f;
        #pragma unroll
        for (int nt = 0; nt < 8; nt++)
            #pragma unroll
            for (int j = 0; j < 4; j++) o[mi][nt][j] = 0.f;
    }

    for (int kt = 0; kt < NT_ATT; kt++) {
        CP_WAIT0();
        __syncthreads();

        // overlap: stream next tile while computing this one
        if (kt + 1 < NT_ATT) {
            int nb = (kt+1) & 1;
            const uint32_t* Kt = Kg + (size_t)(kt+1)*64*64;
            const uint32_t* Vt = Vg + (size_t)(kt+1)*32*64;
            for (int i = tid; i < 1024; i += 128) {
                int r = i >> 4, sg = i & 15;
                cp16(saddr(sKb[nb] + r*AST + sg*4), Kt + r*64 + sg*4);
            }
            for (int i = tid; i < 512; i += 128) {
                int r = i >> 4, sg = i & 15;
                cp16(saddr(sVv[nb] + r*VSTB + sg*4), Vt + r*64 + sg*4);
            }
            CP_COMMIT();
        }

        const uint32_t* sK  = sKb[kt & 1];
        const uint32_t* sVb = sVv[kt & 1];

        // ---- S = Q K^T (tf32): warp computes 32x64 ----
        float sc[2][8][4];
        #pragma unroll
        for (int mi = 0; mi < 2; mi++)
            #pragma unroll
            for (int nt = 0; nt < 8; nt++)
                #pragma unroll
                for (int j = 0; j < 4; j++) sc[mi][nt][j] = 0.f;

        #pragma unroll
        for (int kc = 0; kc < 8; kc++) {
            int cidx = kc*8 + tg;
            uint32_t a0[2], a1[2], a2[2], a3[2];
            #pragma unroll
            for (int mi = 0; mi < 2; mi++) {
                int r = rw + 16*mi + g;
                a0[mi] = sQ[r*AST + cidx];
                a1[mi] = sQ[(r+8)*AST + cidx];
                a2[mi] = sQ[r*AST + cidx + 4];
                a3[mi] = sQ[(r+8)*AST + cidx + 4];
            }
            #pragma unroll
            for (int nt = 0; nt < 8; nt++) {
                uint32_t b0 = sK[(nt*8+g)*AST + cidx];
                uint32_t b1 = sK[(nt*8+g)*AST + cidx + 4];
                mma8(sc[0][nt], a0[0], a1[0], a2[0], a3[0], b0, b1);
                mma8(sc[1][nt], a0[1], a1[1], a2[1], a3[1], b0, b1);
            }
        }

        // ---- online softmax (base-2); P packed to bf16 in registers ----
        uint32_t pb[2][8][2];
        #pragma unroll
        for (int mi = 0; mi < 2; mi++) {
            float t0 = -1e30f, t1 = -1e30f;
            #pragma unroll
            for (int nt = 0; nt < 8; nt++) {
                t0 = fmaxf(t0, fmaxf(sc[mi][nt][0], sc[mi][nt][1]));
                t1 = fmaxf(t1, fmaxf(sc[mi][nt][2], sc[mi][nt][3]));
            }
            t0 = fmaxf(t0, __shfl_xor_sync(0xffffffffu, t0, 1));
            t0 = fmaxf(t0, __shfl_xor_sync(0xffffffffu, t0, 2));
            t1 = fmaxf(t1, __shfl_xor_sync(0xffffffffu, t1, 1));
            t1 = fmaxf(t1, __shfl_xor_sync(0xffffffffu, t1, 2));
            float mn0 = fmaxf(m[mi][0], t0), mn1 = fmaxf(m[mi][1], t1);
            float corr0 = exp2f(m[mi][0] - mn0);
            float corr1 = exp2f(m[mi][1] - mn1);
            m[mi][0] = mn0; m[mi][1] = mn1;

            float rs0 = 0.f, rs1 = 0.f;
            #pragma unroll
            for (int nt = 0; nt < 8; nt++) {
                float e0 = exp2f(sc[mi][nt][0] - mn0);
                float e1 = exp2f(sc[mi][nt][1] - mn0);
                float e2 = exp2f(sc[mi][nt][2] - mn1);
                float e3 = exp2f(sc[mi][nt][3] - mn1);
                rs0 += e0 + e1;
                rs1 += e2 + e3;
                pb[mi][nt][0] = fpack_bf16(e0, e1);
                pb[mi][nt][1] = fpack_bf16(e2, e3);
            }
            rs0 += __shfl_xor_sync(0xffffffffu, rs0, 1);
            rs0 += __shfl_xor_sync(0xffffffffu, rs0, 2);
            rs1 += __shfl_xor_sync(0xffffffffu, rs1, 1);
            rs1 += __shfl_xor_sync(0xffffffffu, rs1, 2);
            l[mi][0] = l[mi][0]*corr0 + rs0;
            l[mi][1] = l[mi][1]*corr1 + rs1;
            #pragma unroll
            for (int nt = 0; nt < 8; nt++) {
                o[mi][nt][0] *= corr0; o[mi][nt][1] *= corr0;
                o[mi][nt][2] *= corr1; o[mi][nt][3] *= corr1;
            }
        }

        // ---- O += P V (bf16, A from registers) ----
        #pragma unroll
        for (int kc = 0; kc < 4; kc++) {
            #pragma unroll
            for (int nt = 0; nt < 8; nt++) {
                uint32_t b0 = sVb[(kc*8+tg)*VSTB   + nt*8 + g];
                uint32_t b1 = sVb[(kc*8+tg+4)*VSTB + nt*8 + g];
                mma16(o[0][nt], pb[0][2*kc][0], pb[0][2*kc][1],
                               pb[0][2*kc+1][0], pb[0][2*kc+1][1], b0, b1);
                mma16(o[1][nt], pb[1][2*kc][0], pb[1][2*kc][1],
                               pb[1][2*kc+1][0], pb[1][2*kc+1][1], b0, b1);
            }
        }
        __syncthreads();   // all warps done reading buffers before next overwrite
    }

    // ---- epilogue: normalize, pre-split bf16 hi/lo, packed pairs along e ----
    const int b = bh >> 4, h = bh & 15;
    #pragma unroll
    for (int mi = 0; mi < 2; mi++) {
        int s0 = qt*128 + rw + 16*mi + g;
        float inv0 = 1.0f / l[mi][0], inv1 = 1.0f / l[mi][1];
        size_t row0 = (size_t)(b*S + s0) * (E/2);
        size_t row1 = (size_t)(b*S + s0 + 8) * (E/2);
        #pragma unroll
        for (int nt = 0; nt < 8; nt++) {
            int widx = h*32 + nt*4 + tg;
            float x0 = o[mi][nt][0]*inv0, x1 = o[mi][nt][1]*inv0;
            float x2 = o[mi][nt][2]*inv1, x3 = o[mi][nt][3]*inv1;
            float h0,l0_,h1,l1_;
            bsplit(x0,h0,l0_); bsplit(x1,h1,l1_);
            g_ah[row0 + widx] = fpack_bf16(h0, h1);
            g_al[row0 + widx] = fpack_bf16(l0_, l1_);
            bsplit(x2,h0,l0_); bsplit(x3,h1,l1_);
            g_ah[row1 + widx] = fpack_bf16(h0, h1);
            g_al[row1 + widx] = fpack_bf16(l0_, l1_);
        }
    }
}

// =====================================================================
// Kernel 3: output projection, split-bf16 (3-term), pure cp.async,
// double-buffered, ktile 32. Tile 128x128 per block.
// =====================================================================
#define OST2 20
#define OPROJ_SMEM (2 * 4 * 128 * OST2 * 4)   // 81,920 B

__global__ void __launch_bounds__(256, 2) oproj_kernel(const float* __restrict__ bo,
                                                       float* __restrict__ out) {
    extern __shared__ uint32_t smu[];
    // per buffer: [sAh | sAl | sWh | sWl], each 128*OST2 words
    const int tid  = threadIdx.x;
    const int w    = tid >> 5;
    const int lane = tid & 31;
    const int g    = lane >> 2;
    const int tg   = lane & 3;
    const int m0   = (w & 3) * 32;
    const int n0   = (w >> 2) * 64;
    const int mg   = blockIdx.y * 128;
    const int ng   = blockIdx.x * 128;
    const int NTO  = E / 32;                    // 32 ktiles

    const uint32_t* srcs[4] = {
        g_ah + (size_t)mg*(E/2), g_al + (size_t)mg*(E/2),
        g_wh + (size_t)ng*(E/2), g_wl + (size_t)ng*(E/2) };

    auto stage = [&](int kt, int bsel) {
        uint32_t* base = smu + bsel * (4*128*OST2);
        for (int i = tid; i < 2048; i += 256) {
            int arr = i >> 9, j = i & 511;
            int r = j >> 2, sg = j & 3;
            cp16(saddr(base + arr*(128*OST2) + r*OST2 + sg*4),
                 srcs[arr] + (size_t)r*(E/2) + kt*16 + sg*4);
        }
        CP_COMMIT();
    };

    float acc[2][8][4];
    #pragma unroll
    for (int mi = 0; mi < 2; mi++)
        #pragma unroll
        for (int nt = 0; nt < 8; nt++)
            #pragma unroll
            for (int j = 0; j < 4; j++) acc[mi][nt][j] = 0.f;

    stage(0, 0);

    for (int kt = 0; kt < NTO; kt++) {
        CP_WAIT0();
        __syncthreads();
        if (kt + 1 < NTO) stage(kt+1, (kt+1) & 1);

        uint32_t* base = smu + (kt & 1) * (4*128*OST2);
        uint32_t* sAh = base;
        uint32_t* sAl = base + 128*OST2;
        uint32_t* sWh = base + 2*128*OST2;
        uint32_t* sWl = base + 3*128*OST2;

        #pragma unroll
        for (int kc = 0; kc < 2; kc++) {
            int cidx = kc*8 + tg;
            uint32_t ah[2][4], al[2][4];
            #pragma unroll
            for (int mi = 0; mi < 2; mi++) {
                int rr = m0 + 16*mi + g;
                ah[mi][0] = sAh[rr*OST2 + cidx];
                ah[mi][1] = sAh[(rr+8)*OST2 + cidx];
                ah[mi][2] = sAh[rr*OST2 + cidx + 4];
                ah[mi][3] = sAh[(rr+8)*OST2 + cidx + 4];
                al[mi][0] = sAl[rr*OST2 + cidx];
                al[mi][1] = sAl[(rr+8)*OST2 + cidx];
                al[mi][2] = sAl[rr*OST2 + cidx + 4];
                al[mi][3] = sAl[(rr+8)*OST2 + cidx + 4];
            }
            #pragma unroll
            for (int nt = 0; nt < 8; nt++) {
                int nr = n0 + nt*8 + g;
                uint32_t bh0 = sWh[nr*OST2 + cidx];
                uint32_t bh1 = sWh[nr*OST2 + cidx + 4];
                uint32_t bl0 = sWl[nr*OST2 + cidx];
                uint32_t bl1 = sWl[nr*OST2 + cidx + 4];
                #pragma unroll
                for (int mi = 0; mi < 2; mi++) {
                    mma16(acc[mi][nt], ah[mi][0], ah[mi][1], ah[mi][2], ah[mi][3], bh0, bh1);
                    mma16(acc[mi][nt], ah[mi][0], ah[mi][1], ah[mi][2], ah[mi][3], bl0, bl1);
                    mma16(acc[mi][nt], al[mi][0], al[mi][1], al[mi][2], al[mi][3], bh0, bh1);
                }
            }
        }
        __syncthreads();   // done reading this buffer
    }

    #pragma unroll
    for (int mi = 0; mi < 2; mi++) {
        int row = mg + m0 + 16*mi + g;
        #pragma unroll
        for (int nt = 0; nt < 8; nt++) {
            int col = ng + n0 + nt*8 + 2*tg;
            float2 bb = *(const float2*)(bo + col);
            *(float2*)(out + (size_t)row*E + col)
                = make_float2(acc[mi][nt][0] + bb.x, acc[mi][nt][1] + bb.y);
            *(float2*)(out + (size_t)(row+8)*E + col)
                = make_float2(acc[mi][nt][2] + bb.x, acc[mi][nt][3] + bb.y);
        }
    }
}

// =====================================================================
extern "C" void kernel_launch(void* const* d_in, const int* in_sizes, int n_in,
                              void* d_out, int out_size) {
    const float* x  = (const float*)d_in[0];
    const float* Wq = (const float*)d_in[1];
    const float* Wk = (const float*)d_in[2];
    const float* Wv = (const float*)d_in[3];
    const float* Wo = (const float*)d_in[4];
    const float* bo = (const float*)d_in[5];
    float* out = (float*)d_out;

    cudaFuncSetAttribute(qkv_kernel,   cudaFuncAttributeMaxDynamicSharedMemorySize, QKV_SMEM);
    cudaFuncSetAttribute(attn_kernel,  cudaFuncAttributeMaxDynamicSharedMemorySize, ATTN_SMEM);
    cudaFuncSetAttribute(oproj_kernel, cudaFuncAttributeMaxDynamicSharedMemorySize, OPROJ_SMEM);

    wsplit_kernel<<<(E*(E/2))/256, 256>>>(Wo);
    qkv_kernel<<<NROW / 128, 512, QKV_SMEM>>>(x, Wq, Wk, Wv);
    attn_kernel<<<dim3(S/128, BH), 128, ATTN_SMEM>>>();
    oproj_kernel<<<dim3(E/128, (B*S)/128), 256, OPROJ_SMEM>>>(bo, out);
}

// round 9
// speedup vs baseline: 4.4282x; 1.0634x over previous
#include <cuda_runtime.h>
#include <cuda_bf16.h>
#include <cstdint>

#define B 2
#define S 2048
#define E 1024
#define H 16
#define D 64
#define BH (B*H)            // 32
#define NROW (B*S*H)        // 65536

// Scratch (allocation-free rule: __device__ globals)
__device__ uint32_t g_q[BH*S*D];        // tf32 bits of q * 0.125*log2(e)
__device__ uint32_t g_k[BH*S*D];        // tf32 bits of k
__device__ uint32_t g_vb[BH*(S/2)*D];   // bf16x2: (V[2p][d], V[2p+1][d])
__device__ uint32_t g_ah[B*S*(E/2)];    // attn out, bf16 hi, packed pairs along e
__device__ uint32_t g_al[B*S*(E/2)];    // attn out, bf16 lo
__device__ uint32_t g_wh[E*(E/2)];      // Wo hi, packed pairs along k
__device__ uint32_t g_wl[E*(E/2)];      // Wo lo

// ---------------------------------------------------------------------
// helpers
// ---------------------------------------------------------------------
__device__ __forceinline__ uint32_t f2t(float f) {
    uint32_t u;
    asm("cvt.rna.tf32.f32 %0, %1;" : "=r"(u) : "f"(f));
    return u;
}
__device__ __forceinline__ uint32_t fpack_bf16(float lo, float hi) {
    __nv_bfloat162 h = __floats2bfloat162_rn(lo, hi);   // .x = lo (low 16 bits)
    return *(uint32_t*)&h;
}
__device__ __forceinline__ void bsplit(float f, float& hi, float& lo) {
    __nv_bfloat16 h = __float2bfloat16_rn(f);
    hi = __bfloat162float(h);
    lo = f - hi;
}
__device__ __forceinline__ uint32_t saddr(const void* p) {
    return (uint32_t)__cvta_generic_to_shared(p);
}
__device__ __forceinline__ void cp16(uint32_t dst, const void* src) {
    asm volatile("cp.async.cg.shared.global [%0], [%1], 16;" :: "r"(dst), "l"(src));
}
#define CP_COMMIT() asm volatile("cp.async.commit_group;")
#define CP_WAIT0()  asm volatile("cp.async.wait_group 0;")

// tf32 m16n8k8
__device__ __forceinline__ void mma8(float* c, uint32_t a0, uint32_t a1,
                                     uint32_t a2, uint32_t a3,
                                     uint32_t b0, uint32_t b1) {
    asm volatile(
        "mma.sync.aligned.m16n8k8.row.col.f32.tf32.tf32.f32 "
        "{%0,%1,%2,%3},{%4,%5,%6,%7},{%8,%9},{%0,%1,%2,%3};"
        : "+f"(c[0]), "+f"(c[1]), "+f"(c[2]), "+f"(c[3])
        : "r"(a0), "r"(a1), "r"(a2), "r"(a3), "r"(b0), "r"(b1));
}
// bf16 m16n8k16
__device__ __forceinline__ void mma16(float* c, uint32_t a0, uint32_t a1,
                                      uint32_t a2, uint32_t a3,
                                      uint32_t b0, uint32_t b1) {
    asm volatile(
        "mma.sync.aligned.m16n8k16.row.col.f32.bf16.bf16.f32 "
        "{%0,%1,%2,%3},{%4,%5,%6,%7},{%8,%9},{%0,%1,%2,%3};"
        : "+f"(c[0]), "+f"(c[1]), "+f"(c[2]), "+f"(c[3])
        : "r"(a0), "r"(a1), "r"(a2), "r"(a3), "r"(b0), "r"(b1));
}

// =====================================================================
// Kernel 0: one-shot Wo split into packed bf16 hi/lo (pairs along k).
// =====================================================================
__global__ void __launch_bounds__(256) wsplit_kernel(const float* __restrict__ Wo) {
    int i = blockIdx.x * 256 + threadIdx.x;        // word index 0..E*E/2-1
    float2 v = *(const float2*)(Wo + 2*(size_t)i);
    float h0,l0,h1,l1;
    bsplit(v.x,h0,l0); bsplit(v.y,h1,l1);
    g_wh[i] = fpack_bf16(h0, h1);
    g_wl[i] = fpack_bf16(l0, l1);
}

// =====================================================================
// Kernel 1: QKV projection, split-bf16 (3-term) MMA. (unchanged)
// =====================================================================
#define QSTB 36
#define QKV_SMEM ((128*QSTB*2 + 192*QSTB*2) * 4 + 128*66*2)   // 109,056 B

__global__ void __launch_bounds__(512, 1) qkv_kernel(const float* __restrict__ x,
                                                     const float* __restrict__ Wq,
                                                     const float* __restrict__ Wk,
                                                     const float* __restrict__ Wv) {
    extern __shared__ uint32_t smu[];
    uint32_t* sXh = smu;                  // [128][QSTB]
    uint32_t* sXl = sXh + 128*QSTB;
    uint32_t* sWh = sXl + 128*QSTB;       // [192][QSTB]
    uint32_t* sWl = sWh + 192*QSTB;
    uint16_t* sVs = (uint16_t*)(sWl + 192*QSTB);   // [128][66] bf16 v staging

    const int tid  = threadIdx.x;
    const int w    = tid >> 5;
    const int lane = tid & 31;
    const int g    = lane >> 2;
    const int tg   = lane & 3;
    const int wr   = w & 7;               // row group
    const int wc   = w >> 3;              // col group (0,1)
    const int g0   = blockIdx.x * 128;
    const float QSC = 0.125f * 1.4426950408889634f;

    for (int i = tid; i < 3072; i += 512) {
        int m = i >> 10, r = (i >> 4) & 63, c4 = (i & 15) << 2;
        const float* Ws = (m == 0) ? Wq : (m == 1) ? Wk : Wv;
        float4 v = *(const float4*)(Ws + r*64 + c4);
        float h0,l0,h1,l1,h2,l2,h3,l3;
        bsplit(v.x,h0,l0); bsplit(v.y,h1,l1); bsplit(v.z,h2,l2); bsplit(v.w,h3,l3);
        int base = (m*64 + r)*QSTB + (c4 >> 1);
        sWh[base]   = fpack_bf16(h0, h1);
        sWh[base+1] = fpack_bf16(h2, h3);
        sWl[base]   = fpack_bf16(l0, l1);
        sWl[base+1] = fpack_bf16(l2, l3);
    }
    for (int i = tid; i < 2048; i += 512) {
        int r = i >> 4, c4 = (i & 15) << 2;
        float4 v = *(const float4*)(x + (size_t)(g0 + r)*64 + c4);
        float h0,l0,h1,l1,h2,l2,h3,l3;
        bsplit(v.x,h0,l0); bsplit(v.y,h1,l1); bsplit(v.z,h2,l2); bsplit(v.w,h3,l3);
        int base = r*QSTB + (c4 >> 1);
        sXh[base]   = fpack_bf16(h0, h1);
        sXh[base+1] = fpack_bf16(h2, h3);
        sXl[base]   = fpack_bf16(l0, l1);
        sXl[base+1] = fpack_bf16(l2, l3);
    }
    __syncthreads();

    float acc[12][4];
    #pragma unroll
    for (int nt = 0; nt < 12; nt++)
        #pragma unroll
        for (int j = 0; j < 4; j++) acc[nt][j] = 0.f;

    const int r0 = 16*wr + g;
    #pragma unroll
    for (int kc = 0; kc < 4; kc++) {
        int cidx = kc*8 + tg;
        uint32_t ah0 = sXh[r0*QSTB + cidx],     ah1 = sXh[(r0+8)*QSTB + cidx];
        uint32_t ah2 = sXh[r0*QSTB + cidx + 4], ah3 = sXh[(r0+8)*QSTB + cidx + 4];
        uint32_t al0 = sXl[r0*QSTB + cidx],     al1 = sXl[(r0+8)*QSTB + cidx];
        uint32_t al2 = sXl[r0*QSTB + cidx + 4], al3 = sXl[(r0+8)*QSTB + cidx + 4];
        #pragma unroll
        for (int nt = 0; nt < 12; nt++) {
            int nr = (wc*12 + nt)*8 + g;
            uint32_t bh0 = sWh[nr*QSTB + cidx], bh1 = sWh[nr*QSTB + cidx + 4];
            uint32_t bl0 = sWl[nr*QSTB + cidx], bl1 = sWl[nr*QSTB + cidx + 4];
            mma16(acc[nt], ah0, ah1, ah2, ah3, bh0, bh1);
            mma16(acc[nt], ah0, ah1, ah2, ah3, bl0, bl1);
            mma16(acc[nt], al0, al1, al2, al3, bh0, bh1);
        }
    }

    int gr0 = g0 + r0, gr1 = gr0 + 8;
    int b0 = gr0 >> 15, s0 = (gr0 & 32767) >> 4, h0 = gr0 & 15;
    int b1 = gr1 >> 15, s1 = (gr1 & 32767) >> 4, h1 = gr1 & 15;
    size_t orow0 = ((size_t)(b0*H + h0)*S + s0) * 64;
    size_t orow1 = ((size_t)(b1*H + h1)*S + s1) * 64;
    #pragma unroll
    for (int nt = 0; nt < 12; nt++) {
        int gn = wc*12 + nt;
        int e  = (gn & 7)*8 + 2*tg;
        if (gn < 16) {
            uint32_t* dst = (gn < 8) ? g_q : g_k;
            float sc_ = (gn < 8) ? QSC : 1.0f;
            *(uint2*)(dst + orow0 + e) = make_uint2(f2t(acc[nt][0]*sc_), f2t(acc[nt][1]*sc_));
            *(uint2*)(dst + orow1 + e) = make_uint2(f2t(acc[nt][2]*sc_), f2t(acc[nt][3]*sc_));
        } else {
            *(uint32_t*)(sVs + r0*66 + e)      = fpack_bf16(acc[nt][0], acc[nt][1]);
            *(uint32_t*)(sVs + (r0+8)*66 + e)  = fpack_bf16(acc[nt][2], acc[nt][3]);
        }
    }
    __syncthreads();

    {
        int b_idx = g0 >> 15;
        int sb    = (g0 & 32767) >> 4;
        for (int wi = tid; wi < 4096; wi += 512) {
            int pr = wi >> 6, e = wi & 63;
            int t = pr >> 4, h = pr & 15;
            int rowA = 32*t + h;
            int rowB = rowA + 16;
            uint32_t a  = sVs[rowA*66 + e];
            uint32_t bq = sVs[rowB*66 + e];
            uint32_t word = (a & 0xffffu) | (bq << 16);
            int bh_ = b_idx*16 + h;
            g_vb[((size_t)bh_*(S/2) + (sb>>1) + t)*64 + e] = word;
        }
    }
}

// =====================================================================
// Kernel 2: flash attention without online max (scores bounded -> fixed
// max=0): no max reduce, no corrections, l reduced once at epilogue.
// Safe cp.async pipeline: WAIT0 -> sync -> stage(kt+1) -> compute(kt).
// =====================================================================
#define AST 68
#define VSTB 72
#define ATTN_SMEM ((128*AST + 2*64*AST + 2*32*VSTB) * 4)   // 88,064 B
#define NT_ATT (S/64)

__global__ void __launch_bounds__(128, 2) attn_kernel() {
    extern __shared__ uint32_t smu[];
    uint32_t* sQ = smu;                                   // [128][AST]
    uint32_t* sKb[2] = { smu + 128*AST, smu + 128*AST + 64*AST };
    uint32_t* sVv[2] = { smu + 128*AST + 2*64*AST,
                         smu + 128*AST + 2*64*AST + 32*VSTB };

    const int tid  = threadIdx.x;
    const int w    = tid >> 5;
    const int lane = tid & 31;
    const int g    = lane >> 2;
    const int tg   = lane & 3;
    const int qt   = blockIdx.x;
    const int bh   = blockIdx.y;

    const uint32_t* Qg = g_q  + (size_t)bh*S*D + (size_t)qt*128*D;
    const uint32_t* Kg = g_k  + (size_t)bh*S*D;
    const uint32_t* Vg = g_vb + (size_t)bh*(S/2)*D;

    // prologue: Q + tile 0 (one async group)
    for (int i = tid; i < 2048; i += 128) {
        int r = i >> 4, sg = i & 15;
        cp16(saddr(sQ + r*AST + sg*4), Qg + r*64 + sg*4);
    }
    for (int i = tid; i < 1024; i += 128) {
        int r = i >> 4, sg = i & 15;
        cp16(saddr(sKb[0] + r*AST + sg*4), Kg + r*64 + sg*4);
    }
    for (int i = tid; i < 512; i += 128) {
        int r = i >> 4, sg = i & 15;
        cp16(saddr(sVv[0] + r*VSTB + sg*4), Vg + r*64 + sg*4);
    }
    CP_COMMIT();

    const int rw = 32*w;
    float l[2][2];            // per-thread partial row sums (reduced at end)
    float o[2][8][4];
    #pragma unroll
    for (int mi = 0; mi < 2; mi++) {
        l[mi][0] = l[mi][1] = 0.f;
        #pragma unroll
        for (int nt = 0; nt < 8; nt++)
            #pragma unroll
            for (int j = 0; j < 4; j++) o[mi][nt][j] = 0.f;
    }

    for (int kt = 0; kt < NT_ATT; kt++) {
        CP_WAIT0();          // this thread's copies for tile kt complete
        __syncthreads();     // visibility to all threads + prior reads of next buffer done

        if (kt + 1 < NT_ATT) {
            // stream next tile during compute of this one
            int nb = (kt+1) & 1;
            const uint32_t* Kt = Kg + (size_t)(kt+1)*64*64;
            const uint32_t* Vt = Vg + (size_t)(kt+1)*32*64;
            for (int i = tid; i < 1024; i += 128) {
                int r = i >> 4, sg = i & 15;
                cp16(saddr(sKb[nb] + r*AST + sg*4), Kt + r*64 + sg*4);
            }
            for (int i = tid; i < 512; i += 128) {
                int r = i >> 4, sg = i & 15;
                cp16(saddr(sVv[nb] + r*VSTB + sg*4), Vt + r*64 + sg*4);
            }
            CP_COMMIT();
        }

        const uint32_t* sK  = sKb[kt & 1];
        const uint32_t* sVb = sVv[kt & 1];

        // ---- S = Q K^T (tf32): warp computes 32x64 ----
        float sc[2][8][4];
        #pragma unroll
        for (int mi = 0; mi < 2; mi++)
            #pragma unroll
            for (int nt = 0; nt < 8; nt++)
                #pragma unroll
                for (int j = 0; j < 4; j++) sc[mi][nt][j] = 0.f;

        #pragma unroll
        for (int kc = 0; kc < 8; kc++) {
            int cidx = kc*8 + tg;
            uint32_t a0[2], a1[2], a2[2], a3[2];
            #pragma unroll
            for (int mi = 0; mi < 2; mi++) {
                int r = rw + 16*mi + g;
                a0[mi] = sQ[r*AST + cidx];
                a1[mi] = sQ[(r+8)*AST + cidx];
                a2[mi] = sQ[r*AST + cidx + 4];
                a3[mi] = sQ[(r+8)*AST + cidx + 4];
            }
            #pragma unroll
            for (int nt = 0; nt < 8; nt++) {
                uint32_t b0 = sK[(nt*8+g)*AST + cidx];
                uint32_t b1 = sK[(nt*8+g)*AST + cidx + 4];
                mma8(sc[0][nt], a0[0], a1[0], a2[0], a3[0], b0, b1);
                mma8(sc[1][nt], a0[1], a1[1], a2[1], a3[1], b0, b1);
            }
        }

        // ---- softmax numerator (base-2, fixed max=0; bounded scores) ----
        uint32_t pb[2][8][2];
        #pragma unroll
        for (int mi = 0; mi < 2; mi++) {
            float rs0 = 0.f, rs1 = 0.f;
            #pragma unroll
            for (int nt = 0; nt < 8; nt++) {
                float e0 = exp2f(sc[mi][nt][0]);
                float e1 = exp2f(sc[mi][nt][1]);
                float e2 = exp2f(sc[mi][nt][2]);
                float e3 = exp2f(sc[mi][nt][3]);
                rs0 += e0 + e1;
                rs1 += e2 + e3;
                pb[mi][nt][0] = fpack_bf16(e0, e1);
                pb[mi][nt][1] = fpack_bf16(e2, e3);
            }
            l[mi][0] += rs0;
            l[mi][1] += rs1;
        }

        // ---- O += P V (bf16, A from registers) ----
        #pragma unroll
        for (int kc = 0; kc < 4; kc++) {
            #pragma unroll
            for (int nt = 0; nt < 8; nt++) {
                uint32_t b0 = sVb[(kc*8+tg)*VSTB   + nt*8 + g];
                uint32_t b1 = sVb[(kc*8+tg+4)*VSTB + nt*8 + g];
                mma16(o[0][nt], pb[0][2*kc][0], pb[0][2*kc][1],
                               pb[0][2*kc+1][0], pb[0][2*kc+1][1], b0, b1);
                mma16(o[1][nt], pb[1][2*kc][0], pb[1][2*kc][1],
                               pb[1][2*kc+1][0], pb[1][2*kc+1][1], b0, b1);
            }
        }
    }

    // ---- epilogue: reduce l once, normalize, pre-split bf16 hi/lo ----
    #pragma unroll
    for (int mi = 0; mi < 2; mi++) {
        #pragma unroll
        for (int j = 0; j < 2; j++) {
            l[mi][j] += __shfl_xor_sync(0xffffffffu, l[mi][j], 1);
            l[mi][j] += __shfl_xor_sync(0xffffffffu, l[mi][j], 2);
        }
    }
    const int b = bh >> 4, h = bh & 15;
    #pragma unroll
    for (int mi = 0; mi < 2; mi++) {
        int s0 = qt*128 + rw + 16*mi + g;
        float inv0 = 1.0f / l[mi][0], inv1 = 1.0f / l[mi][1];
        size_t row0 = (size_t)(b*S + s0) * (E/2);
        size_t row1 = (size_t)(b*S + s0 + 8) * (E/2);
        #pragma unroll
        for (int nt = 0; nt < 8; nt++) {
            int widx = h*32 + nt*4 + tg;
            float x0 = o[mi][nt][0]*inv0, x1 = o[mi][nt][1]*inv0;
            float x2 = o[mi][nt][2]*inv1, x3 = o[mi][nt][3]*inv1;
            float h0,l0_,h1,l1_;
            bsplit(x0,h0,l0_); bsplit(x1,h1,l1_);
            g_ah[row0 + widx] = fpack_bf16(h0, h1);
            g_al[row0 + widx] = fpack_bf16(l0_, l1_);
            bsplit(x2,h0,l0_); bsplit(x3,h1,l1_);
            g_ah[row1 + widx] = fpack_bf16(h0, h1);
            g_al[row1 + widx] = fpack_bf16(l0_, l1_);
        }
    }
}

// =====================================================================
// Kernel 3: output projection, split-bf16 (3-term), safe cp.async
// pipeline (WAIT0 -> sync -> stage -> compute). ktile 32.
// =====================================================================
#define OST2 20
#define OPROJ_SMEM (2 * 4 * 128 * OST2 * 4)   // 81,920 B

__global__ void __launch_bounds__(256, 2) oproj_kernel(const float* __restrict__ bo,
                                                       float* __restrict__ out) {
    extern __shared__ uint32_t smu[];
    const int tid  = threadIdx.x;
    const int w    = tid >> 5;
    const int lane = tid & 31;
    const int g    = lane >> 2;
    const int tg   = lane & 3;
    const int m0   = (w & 3) * 32;
    const int n0   = (w >> 2) * 64;
    const int mg   = blockIdx.y * 128;
    const int ng   = blockIdx.x * 128;
    const int NTO  = E / 32;                    // 32 ktiles

    const uint32_t* srcs[4] = {
        g_ah + (size_t)mg*(E/2), g_al + (size_t)mg*(E/2),
        g_wh + (size_t)ng*(E/2), g_wl + (size_t)ng*(E/2) };

    auto stage = [&](int kt, int bsel) {
        uint32_t* base = smu + bsel * (4*128*OST2);
        for (int i = tid; i < 2048; i += 256) {
            int arr = i >> 9, j = i & 511;
            int r = j >> 2, sg = j & 3;
            cp16(saddr(base + arr*(128*OST2) + r*OST2 + sg*4),
                 srcs[arr] + (size_t)r*(E/2) + kt*16 + sg*4);
        }
        CP_COMMIT();
    };

    float acc[2][8][4];
    #pragma unroll
    for (int mi = 0; mi < 2; mi++)
        #pragma unroll
        for (int nt = 0; nt < 8; nt++)
            #pragma unroll
            for (int j = 0; j < 4; j++) acc[mi][nt][j] = 0.f;

    stage(0, 0);

    for (int kt = 0; kt < NTO; kt++) {
        CP_WAIT0();          // tile kt's copies complete (this thread)
        __syncthreads();     // visibility + prior reads of next buffer done

        if (kt + 1 < NTO) stage(kt+1, (kt+1) & 1);   // overlaps compute below

        uint32_t* base = smu + (kt & 1) * (4*128*OST2);
        uint32_t* sAh = base;
        uint32_t* sAl = base + 128*OST2;
        uint32_t* sWh = base + 2*128*OST2;
        uint32_t* sWl = base + 3*128*OST2;

        #pragma unroll
        for (int kc = 0; kc < 2; kc++) {
            int cidx = kc*8 + tg;
            uint32_t ah[2][4], al[2][4];
            #pragma unroll
            for (int mi = 0; mi < 2; mi++) {
                int rr = m0 + 16*mi + g;
                ah[mi][0] = sAh[rr*OST2 + cidx];
                ah[mi][1] = sAh[(rr+8)*OST2 + cidx];
                ah[mi][2] = sAh[rr*OST2 + cidx + 4];
                ah[mi][3] = sAh[(rr+8)*OST2 + cidx + 4];
                al[mi][0] = sAl[rr*OST2 + cidx];
                al[mi][1] = sAl[(rr+8)*OST2 + cidx];
                al[mi][2] = sAl[rr*OST2 + cidx + 4];
                al[mi][3] = sAl[(rr+8)*OST2 + cidx + 4];
            }
            #pragma unroll
            for (int nt = 0; nt < 8; nt++) {
                int nr = n0 + nt*8 + g;
                uint32_t bh0 = sWh[nr*OST2 + cidx];
                uint32_t bh1 = sWh[nr*OST2 + cidx + 4];
                uint32_t bl0 = sWl[nr*OST2 + cidx];
                uint32_t bl1 = sWl[nr*OST2 + cidx + 4];
                #pragma unroll
                for (int mi = 0; mi < 2; mi++) {
                    mma16(acc[mi][nt], ah[mi][0], ah[mi][1], ah[mi][2], ah[mi][3], bh0, bh1);
                    mma16(acc[mi][nt], ah[mi][0], ah[mi][1], ah[mi][2], ah[mi][3], bl0, bl1);
                    mma16(acc[mi][nt], al[mi][0], al[mi][1], al[mi][2], al[mi][3], bh0, bh1);
                }
            }
        }
    }

    #pragma unroll
    for (int mi = 0; mi < 2; mi++) {
        int row = mg + m0 + 16*mi + g;
        #pragma unroll
        for (int nt = 0; nt < 8; nt++) {
            int col = ng + n0 + nt*8 + 2*tg;
            float2 bb = *(const float2*)(bo + col);
            *(float2*)(out + (size_t)row*E + col)
                = make_float2(acc[mi][nt][0] + bb.x, acc[mi][nt][1] + bb.y);
            *(float2*)(out + (size_t)(row+8)*E + col)
                = make_float2(acc[mi][nt][2] + bb.x, acc[mi][nt][3] + bb.y);
        }
    }
}

// =====================================================================
extern "C" void kernel_launch(void* const* d_in, const int* in_sizes, int n_in,
                              void* d_out, int out_size) {
    const float* x  = (const float*)d_in[0];
    const float* Wq = (const float*)d_in[1];
    const float* Wk = (const float*)d_in[2];
    const float* Wv = (const float*)d_in[3];
    const float* Wo = (const float*)d_in[4];
    const float* bo = (const float*)d_in[5];
    float* out = (float*)d_out;

    cudaFuncSetAttribute(qkv_kernel,   cudaFuncAttributeMaxDynamicSharedMemorySize, QKV_SMEM);
    cudaFuncSetAttribute(attn_kernel,  cudaFuncAttributeMaxDynamicSharedMemorySize, ATTN_SMEM);
    cudaFuncSetAttribute(oproj_kernel, cudaFuncAttributeMaxDynamicSharedMemorySize, OPROJ_SMEM);

    wsplit_kernel<<<(E*(E/2))/256, 256>>>(Wo);
    qkv_kernel<<<NROW / 128, 512, QKV_SMEM>>>(x, Wq, Wk, Wv);
    attn_kernel<<<dim3(S/128, BH), 128, ATTN_SMEM>>>();
    oproj_kernel<<<dim3(E/128, (B*S)/128), 256, OPROJ_SMEM>>>(bo, out);
}